// round 8
// baseline (speedup 1.0000x reference)
#include <cuda_runtime.h>
#include <cuda_bf16.h>
#include <stdint.h>
#include <math.h>

#define TT 2048
#define HDIM 2048
#define NHEADS 32
#define NKVH 8
#define HEADD 64
#define SWIN 128
#define QKVD 3072   // HEADD * (NHEADS + 2*NKVH)

typedef __nv_bfloat16 bf16;

// ---------------- scratch (device globals; no allocation allowed) ----------------
__device__ float g_qkv[(size_t)TT * QKVD];
__device__ bf16 g_nhi[TT * HDIM];              // rmsnorm out, bf16 hi
__device__ bf16 g_nlo[TT * HDIM];              // rmsnorm out, bf16 lo
__device__ bf16 g_ahi[TT * HDIM];              // attention out, bf16 hi
__device__ bf16 g_alo[TT * HDIM];              // attention out, bf16 lo
__device__ bf16 g_wqhi[(size_t)HDIM * QKVD];   // qkv weight hi, transposed [N][K]
__device__ bf16 g_wqlo[(size_t)HDIM * QKVD];   // qkv weight lo, transposed [N][K]
__device__ bf16 g_wohi[(size_t)HDIM * HDIM];   // out weight hi, transposed
__device__ bf16 g_wolo[(size_t)HDIM * HDIM];   // out weight lo, transposed

__device__ __forceinline__ void splitb(float v, bf16& hi, bf16& lo) {
    hi = __float2bfloat16(v);
    lo = __float2bfloat16(v - __bfloat162float(hi));
}

// ---------------- weight split + transpose: W[K][N] fp32 -> Whi/Wlo[N][K] bf16 --
__global__ void splitw_t(const float* __restrict__ W,
                         bf16* __restrict__ Whi, bf16* __restrict__ Wlo,
                         int K, int N) {
    __shared__ float tile[32][33];
    const int kb = blockIdx.y * 32, nb = blockIdx.x * 32;
    const int tx = threadIdx.x, ty = threadIdx.y;   // 32 x 8
    #pragma unroll
    for (int i = 0; i < 32; i += 8)
        tile[ty + i][tx] = W[(size_t)(kb + ty + i) * N + nb + tx];
    __syncthreads();
    #pragma unroll
    for (int i = 0; i < 32; i += 8) {
        int n = nb + ty + i, k = kb + tx;
        float v = tile[tx][ty + i];
        bf16 h, l;
        splitb(v, h, l);
        Whi[(size_t)n * K + k] = h;
        Wlo[(size_t)n * K + k] = l;
    }
}

// ---------------- RMSNorm (writes pre-split bf16 hi/lo) ----------------
__global__ void rmsnorm_kernel(const float* __restrict__ x,
                               const float* __restrict__ scale) {
    int t = blockIdx.x;
    const float* row = x + (size_t)t * HDIM;
    float ss = 0.f;
    for (int i = threadIdx.x; i < HDIM; i += blockDim.x) {
        float v = row[i];
        ss += v * v;
    }
    __shared__ float sh[9];
    #pragma unroll
    for (int o = 16; o; o >>= 1) ss += __shfl_xor_sync(0xffffffffu, ss, o);
    int lane = threadIdx.x & 31, wid = threadIdx.x >> 5;
    if (lane == 0) sh[wid] = ss;
    __syncthreads();
    if (threadIdx.x == 0) {
        float s = 0.f;
        for (int i = 0; i < (int)(blockDim.x >> 5); i++) s += sh[i];
        sh[8] = rsqrtf(s / (float)HDIM + 1e-5f);
    }
    __syncthreads();
    float inv = sh[8];
    for (int i = threadIdx.x; i < HDIM; i += blockDim.x) {
        float v = row[i] * inv * scale[i];
        bf16 h, l;
        splitb(v, h, l);
        g_nhi[(size_t)t * HDIM + i] = h;
        g_nlo[(size_t)t * HDIM + i] = l;
    }
}

// ---------------- split-bf16 tensor-core GEMM (2-stage, 2 CTAs/SM) -------------
// C[M,N] = A[M,K]@B[K,N] via AhiBhi + AhiBlo + AloBhi, mma.m16n8k16.bf16.
// A stored [M][K] bf16 hi/lo; B stored transposed [N][K] bf16 hi/lo.
// BM=BN=128, BK=32, 512 threads, warp grid 4x4, warp tile 32x32.

#define MMAB(d, a, b0, b1) asm volatile( \
  "mma.sync.aligned.m16n8k16.row.col.f32.bf16.bf16.f32 " \
  "{%0,%1,%2,%3},{%4,%5,%6,%7},{%8,%9},{%0,%1,%2,%3};\n" \
  : "+f"((d)[0]), "+f"((d)[1]), "+f"((d)[2]), "+f"((d)[3]) \
  : "r"((a)[0]), "r"((a)[1]), "r"((a)[2]), "r"((a)[3]), \
    "r"(b0), "r"(b1))

#define LDSM4(r, addr) asm volatile( \
  "ldmatrix.sync.aligned.m8n8.x4.shared.b16 {%0,%1,%2,%3}, [%4];" \
  : "=r"((r)[0]), "=r"((r)[1]), "=r"((r)[2]), "=r"((r)[3]) : "r"(addr))

#define SROWB 80u                 // padded row stride in bytes (40 bf16)
#define SAB   (128u * SROWB)      // 10240 B per array
#define STAGEB (4u * SAB)         // 40960 B per stage (Ahi,Alo,Bhi,Blo)
#define GSMEM_BYTES (2 * STAGEB)  // 81920 -> 2 CTAs/SM fit in 228KB

extern __shared__ unsigned char dynsm[];

__global__ __launch_bounds__(512, 2) void gemm_bf16(
    const bf16* __restrict__ Ahi, const bf16* __restrict__ Alo,
    const bf16* __restrict__ Bhi, const bf16* __restrict__ Blo,
    const float* __restrict__ bias, const float* __restrict__ resid,
    float* __restrict__ C, int N, int K)
{
    const int tid  = threadIdx.x;
    const int lane = tid & 31;
    const int wid  = tid >> 5;
    const int grp  = lane >> 2;        // 0..7
    const int qid  = lane & 3;         // 0..3
    const int wm   = (wid >> 2) * 32;
    const int wn   = (wid & 3) * 32;
    const int m0 = blockIdx.y * 128;
    const int n0 = blockIdx.x * 128;

    uint32_t smb;
    asm("{ .reg .u64 t; cvta.to.shared.u64 t, %1; cvt.u32.u64 %0, t; }"
        : "=r"(smb) : "l"(dynsm));

    float acc[2][4][4];
    #pragma unroll
    for (int i = 0; i < 2; i++)
        #pragma unroll
        for (int j = 0; j < 4; j++)
            #pragma unroll
            for (int r = 0; r < 4; r++) acc[i][j][r] = 0.f;

    // cp.async mapping: 4 lanes per row (64B row), rows tid>>2
    const int lrow = tid >> 2, lc16 = tid & 3;

    auto load_stage = [&](int stage, int t) {
        const int k0 = t << 5;
        const uint32_t sb = smb + stage * STAGEB;
        {
            const bf16* src = Ahi + (size_t)(m0 + lrow) * K + k0 + lc16 * 8;
            uint32_t dst = sb + lrow * SROWB + lc16 * 16;
            asm volatile("cp.async.cg.shared.global [%0], [%1], 16;" :: "r"(dst), "l"(src));
        }
        {
            const bf16* src = Alo + (size_t)(m0 + lrow) * K + k0 + lc16 * 8;
            uint32_t dst = sb + SAB + lrow * SROWB + lc16 * 16;
            asm volatile("cp.async.cg.shared.global [%0], [%1], 16;" :: "r"(dst), "l"(src));
        }
        {
            const bf16* src = Bhi + (size_t)(n0 + lrow) * K + k0 + lc16 * 8;
            uint32_t dst = sb + 2 * SAB + lrow * SROWB + lc16 * 16;
            asm volatile("cp.async.cg.shared.global [%0], [%1], 16;" :: "r"(dst), "l"(src));
        }
        {
            const bf16* src = Blo + (size_t)(n0 + lrow) * K + k0 + lc16 * 8;
            uint32_t dst = sb + 3 * SAB + lrow * SROWB + lc16 * 16;
            asm volatile("cp.async.cg.shared.global [%0], [%1], 16;" :: "r"(dst), "l"(src));
        }
        asm volatile("cp.async.commit_group;");
    };

    // ldmatrix per-lane offsets: row = lane&15, khalf = lane>>4
    const uint32_t lmrow  = lane & 15;
    const uint32_t lmkh   = (lane >> 4) * 16;   // byte offset for k-half
    const uint32_t aoff0 = (wm + 0  + lmrow) * SROWB + lmkh;
    const uint32_t aoff1 = (wm + 16 + lmrow) * SROWB + lmkh;
    const uint32_t boff0 = (wn + 0  + lmrow) * SROWB + lmkh;
    const uint32_t boff1 = (wn + 16 + lmrow) * SROWB + lmkh;

    const int trips = K >> 5;          // 64
    load_stage(0, 0);
    load_stage(1, 1);

    for (int t = 0; t < trips; t++) {
        if (t < trips - 1) asm volatile("cp.async.wait_group 1;");
        else               asm volatile("cp.async.wait_group 0;");
        __syncthreads();

        const uint32_t sb = smb + (t & 1) * STAGEB;
        #pragma unroll
        for (int ks = 0; ks < 2; ks++) {
            const uint32_t ko = ks * 32;   // 16 bf16 = 32 bytes
            uint32_t ah[2][4], al[2][4];
            LDSM4(ah[0], sb + aoff0 + ko);
            LDSM4(ah[1], sb + aoff1 + ko);
            LDSM4(al[0], sb + SAB + aoff0 + ko);
            LDSM4(al[1], sb + SAB + aoff1 + ko);
            #pragma unroll
            for (int np = 0; np < 2; np++) {
                uint32_t bh[4], bl[4];
                LDSM4(bh, sb + 2 * SAB + (np ? boff1 : boff0) + ko);
                LDSM4(bl, sb + 3 * SAB + (np ? boff1 : boff0) + ko);
                #pragma unroll
                for (int mt = 0; mt < 2; mt++) {
                    #pragma unroll
                    for (int sub = 0; sub < 2; sub++) {
                        float* d = acc[mt][np * 2 + sub];
                        MMAB(d, ah[mt], bh[sub], bh[sub + 2]);
                        MMAB(d, ah[mt], bl[sub], bl[sub + 2]);
                        MMAB(d, al[mt], bh[sub], bh[sub + 2]);
                    }
                }
            }
        }
        __syncthreads();
        if (t + 2 < trips) load_stage(t & 1, t + 2);
    }

    #pragma unroll
    for (int mt = 0; mt < 2; mt++) {
        int r0 = m0 + wm + mt * 16 + grp;
        #pragma unroll
        for (int nt = 0; nt < 4; nt++) {
            int c = n0 + wn + nt * 8 + qid * 2;
            float2 bb = *(const float2*)&bias[c];
            float2 v0 = make_float2(acc[mt][nt][0] + bb.x, acc[mt][nt][1] + bb.y);
            float2 v1 = make_float2(acc[mt][nt][2] + bb.x, acc[mt][nt][3] + bb.y);
            if (resid) {
                float2 ra = *(const float2*)&resid[(size_t)r0 * N + c];
                float2 rb = *(const float2*)&resid[(size_t)(r0 + 8) * N + c];
                v0.x += ra.x; v0.y += ra.y; v1.x += rb.x; v1.y += rb.y;
            }
            *(float2*)&C[(size_t)r0 * N + c]       = v0;
            *(float2*)&C[(size_t)(r0 + 8) * N + c] = v1;
        }
    }
}

// ---------------- RoPE (in-place on g_qkv) ----------------
__global__ void rope_kernel(const float* __restrict__ cos_t,
                            const float* __restrict__ sin_t) {
    int t = blockIdx.x;
    const float* c = cos_t + t * 32;
    const float* s = sin_t + t * 32;
    float* rowbase = g_qkv + (size_t)t * QKVD;
    for (int i = threadIdx.x; i < 40 * 32; i += blockDim.x) {
        int head = i >> 5, r = i & 31;
        float* base = rowbase + head * HEADD;
        float x1 = base[r], x2 = base[r + 32];
        float cv = c[r], sv = s[r];
        base[r]      = x1 * cv - x2 * sv;
        base[r + 32] = x2 * cv + x1 * sv;
    }
}

// ---------------- tiled sliding-window GQA attention with sink ----------------
#define KMAX 160
#define KT_STRIDE 164
#define V_STRIDE 68
#define OFF_KT 0
#define OFF_V  (64 * KT_STRIDE)
#define OFF_Q  (OFF_V + KMAX * V_STRIDE)
#define OFF_S  (OFF_Q + 4 * 32 * 64)
#define ATT_SMEM_FLOATS (OFF_S + 16 * KT_STRIDE)

__global__ __launch_bounds__(512, 1) void attn3_kernel(const float* __restrict__ sinks) {
    float* smf = (float*)dynsm;
    float* KsT = smf + OFF_KT;
    float* Vs  = smf + OFF_V;
    float* Qs  = smf + OFF_Q;
    float* S   = smf + OFF_S;

    const int qt = blockIdx.x;
    const int n  = blockIdx.y;
    const int q0 = qt * 32;
    const int k0 = (q0 - SWIN > 0) ? (q0 - SWIN) : 0;
    const int kcnt = q0 + 32 - k0;
    const int tid = threadIdx.x;
    const int lane = tid & 31, wid = tid >> 5;

    const float* kbase = g_qkv + (size_t)k0 * QKVD + NHEADS * HEADD + n * HEADD;
    const float* vbase = kbase + NKVH * HEADD;

    for (int f = tid; f < kcnt * 16; f += 512) {
        int r = f >> 4, dq = (f & 15) * 4;
        float4 kv = *(const float4*)(kbase + (size_t)r * QKVD + dq);
        KsT[(dq + 0) * KT_STRIDE + r] = kv.x;
        KsT[(dq + 1) * KT_STRIDE + r] = kv.y;
        KsT[(dq + 2) * KT_STRIDE + r] = kv.z;
        KsT[(dq + 3) * KT_STRIDE + r] = kv.w;
        float4 vv = *(const float4*)(vbase + (size_t)r * QKVD + dq);
        *(float4*)&Vs[r * V_STRIDE + dq] = vv;
    }
    for (int f = tid; f < 4 * 32 * 16; f += 512) {
        int g = f >> 9, r = (f >> 4) & 31, dq = (f & 15) * 4;
        *(float4*)&Qs[(g * 32 + r) * 64 + dq] =
            *(const float4*)(g_qkv + (size_t)(q0 + r) * QKVD + (n * 4 + g) * HEADD + dq);
    }
    __syncthreads();

    const int g  = wid & 3;
    const int ww = wid >> 2;
    const int h  = n * 4 + g;
    const float snk = sinks[h];
    float* Sw = S + wid * KT_STRIDE;

    #pragma unroll
    for (int qq = 0; qq < 8; qq++) {
        const int qi = ww * 8 + qq;
        const int qg = q0 + qi;
        const int khi = qg - k0;
        int klo = qg - SWIN - k0; if (klo < 0) klo = 0;
        const float* qrow = Qs + (g * 32 + qi) * 64;
        float lmax = -INFINITY;

        for (int kb = lane; kb < 40; kb += 32) {
            const int kk = kb * 4;
            float s0 = 0.f, s1 = 0.f, s2 = 0.f, s3 = 0.f;
            #pragma unroll
            for (int d = 0; d < 64; d += 4) {
                float4 q4 = *(const float4*)(qrow + d);
                float4 kv;
                kv = *(const float4*)&KsT[(d + 0) * KT_STRIDE + kk];
                s0 += q4.x * kv.x; s1 += q4.x * kv.y; s2 += q4.x * kv.z; s3 += q4.x * kv.w;
                kv = *(const float4*)&KsT[(d + 1) * KT_STRIDE + kk];
                s0 += q4.y * kv.x; s1 += q4.y * kv.y; s2 += q4.y * kv.z; s3 += q4.y * kv.w;
                kv = *(const float4*)&KsT[(d + 2) * KT_STRIDE + kk];
                s0 += q4.z * kv.x; s1 += q4.z * kv.y; s2 += q4.z * kv.z; s3 += q4.z * kv.w;
                kv = *(const float4*)&KsT[(d + 3) * KT_STRIDE + kk];
                s0 += q4.w * kv.x; s1 += q4.w * kv.y; s2 += q4.w * kv.z; s3 += q4.w * kv.w;
            }
            float v0 = (kk + 0 >= klo && kk + 0 <= khi) ? s0 * 0.125f : -INFINITY;
            float v1 = (kk + 1 >= klo && kk + 1 <= khi) ? s1 * 0.125f : -INFINITY;
            float v2 = (kk + 2 >= klo && kk + 2 <= khi) ? s2 * 0.125f : -INFINITY;
            float v3 = (kk + 3 >= klo && kk + 3 <= khi) ? s3 * 0.125f : -INFINITY;
            *(float4*)&Sw[kk] = make_float4(v0, v1, v2, v3);
            lmax = fmaxf(lmax, fmaxf(fmaxf(v0, v1), fmaxf(v2, v3)));
        }
        #pragma unroll
        for (int o = 16; o; o >>= 1)
            lmax = fmaxf(lmax, __shfl_xor_sync(0xffffffffu, lmax, o));
        lmax = fmaxf(lmax, snk);

        float lsum = 0.f;
        for (int k = lane; k < KMAX; k += 32) {
            float e = expf(Sw[k] - lmax);
            Sw[k] = e;
            lsum += e;
        }
        #pragma unroll
        for (int o = 16; o; o >>= 1)
            lsum += __shfl_xor_sync(0xffffffffu, lsum, o);
        const float inv = 1.f / (lsum + expf(snk - lmax));

        float a0 = 0.f, a1 = 0.f;
        const int d0 = lane, d1 = lane + 32;
        #pragma unroll 4
        for (int k = 0; k < kcnt; k++) {
            float p = Sw[k];
            a0 += p * Vs[k * V_STRIDE + d0];
            a1 += p * Vs[k * V_STRIDE + d1];
        }
        float r0 = a0 * inv, r1 = a1 * inv;
        bf16 h0, l0, h1, l1;
        splitb(r0, h0, l0);
        splitb(r1, h1, l1);
        size_t o0 = (size_t)qg * HDIM + h * HEADD;
        g_ahi[o0 + d0] = h0; g_alo[o0 + d0] = l0;
        g_ahi[o0 + d1] = h1; g_alo[o0 + d1] = l1;
    }
}

// ---------------- launch ----------------
extern "C" void kernel_launch(void* const* d_in, const int* in_sizes, int n_in,
                              void* d_out, int out_size) {
    const float* x          = (const float*)d_in[0];
    const float* scale      = (const float*)d_in[1];
    const float* sinks      = (const float*)d_in[2];
    const float* qkv_kernel = (const float*)d_in[3];
    const float* qkv_bias   = (const float*)d_in[4];
    const float* out_kernel = (const float*)d_in[5];
    const float* out_bias   = (const float*)d_in[6];
    const float* cos_t      = (const float*)d_in[7];
    const float* sin_t      = (const float*)d_in[8];
    // d_in[9] = mask: unused (sliding window applied structurally)
    float* out = (float*)d_out;

    void *p_qkv, *p_nhi, *p_nlo, *p_ahi, *p_alo, *p_wqhi, *p_wqlo, *p_wohi, *p_wolo;
    cudaGetSymbolAddress(&p_qkv, g_qkv);
    cudaGetSymbolAddress(&p_nhi, g_nhi);
    cudaGetSymbolAddress(&p_nlo, g_nlo);
    cudaGetSymbolAddress(&p_ahi, g_ahi);
    cudaGetSymbolAddress(&p_alo, g_alo);
    cudaGetSymbolAddress(&p_wqhi, g_wqhi);
    cudaGetSymbolAddress(&p_wqlo, g_wqlo);
    cudaGetSymbolAddress(&p_wohi, g_wohi);
    cudaGetSymbolAddress(&p_wolo, g_wolo);

    static bool attr_set = false;
    if (!attr_set) {
        cudaFuncSetAttribute(gemm_bf16,
                             cudaFuncAttributeMaxDynamicSharedMemorySize,
                             GSMEM_BYTES);
        cudaFuncSetAttribute(attn3_kernel,
                             cudaFuncAttributeMaxDynamicSharedMemorySize,
                             ATT_SMEM_FLOATS * 4);
        attr_set = true;
    }

    // pre-split + transpose weights to bf16 hi/lo, [N][K]
    splitw_t<<<dim3(QKVD / 32, HDIM / 32), dim3(32, 8)>>>(
        qkv_kernel, (bf16*)p_wqhi, (bf16*)p_wqlo, HDIM, QKVD);
    splitw_t<<<dim3(HDIM / 32, HDIM / 32), dim3(32, 8)>>>(
        out_kernel, (bf16*)p_wohi, (bf16*)p_wolo, HDIM, HDIM);

    rmsnorm_kernel<<<TT, 256>>>(x, scale);

    // QKV: [2048,2048] @ [2048,3072]
    gemm_bf16<<<dim3(QKVD / 128, TT / 128), 512, GSMEM_BYTES>>>(
        (const bf16*)p_nhi, (const bf16*)p_nlo,
        (const bf16*)p_wqhi, (const bf16*)p_wqlo,
        qkv_bias, nullptr, (float*)p_qkv, QKVD, HDIM);

    rope_kernel<<<TT, 256>>>(cos_t, sin_t);

    attn3_kernel<<<dim3(TT / 32, NKVH), 512, ATT_SMEM_FLOATS * 4>>>(sinks);

    // out-proj + residual: [2048,2048] @ [2048,2048] + x
    gemm_bf16<<<dim3(HDIM / 128, TT / 128), 512, GSMEM_BYTES>>>(
        (const bf16*)p_ahi, (const bf16*)p_alo,
        (const bf16*)p_wohi, (const bf16*)p_wolo,
        out_bias, x, out, HDIM, HDIM);
}

// round 9
// speedup vs baseline: 1.3140x; 1.3140x over previous
#include <cuda_runtime.h>
#include <cuda_bf16.h>
#include <cuda_fp16.h>
#include <stdint.h>
#include <math.h>

#define TT 2048
#define HDIM 2048
#define NHEADS 32
#define NKVH 8
#define HEADD 64
#define SWIN 128
#define QKVD 3072   // HEADD * (NHEADS + 2*NKVH)

typedef __nv_bfloat16 bf16;

// ---------------- scratch (device globals; no allocation allowed) ----------------
__device__ float g_qkv[(size_t)TT * QKVD];
__device__ bf16 g_nhi[TT * HDIM];              // rmsnorm out, bf16 hi
__device__ bf16 g_nlo[TT * HDIM];              // rmsnorm out, bf16 lo
__device__ __half g_ahi[TT * HDIM];            // attention out, fp16 hi
__device__ __half g_alo[TT * HDIM];            // attention out, fp16 lo
__device__ bf16 g_wqhi[(size_t)HDIM * QKVD];   // qkv weight hi, transposed [N][K]
__device__ bf16 g_wqlo[(size_t)HDIM * QKVD];   // qkv weight lo, transposed [N][K]
__device__ __half g_woh[(size_t)HDIM * HDIM];  // out weight fp16, transposed [N][K]

__device__ __forceinline__ void splitb(float v, bf16& hi, bf16& lo) {
    hi = __float2bfloat16(v);
    lo = __float2bfloat16(v - __bfloat162float(hi));
}
__device__ __forceinline__ void splith(float v, __half& hi, __half& lo) {
    hi = __float2half(v);
    lo = __float2half(v - __half2float(hi));
}

// ---------------- weight split + transpose: W[K][N] fp32 -> Whi/Wlo[N][K] bf16 --
__global__ void splitw_t(const float* __restrict__ W,
                         bf16* __restrict__ Whi, bf16* __restrict__ Wlo,
                         int K, int N) {
    __shared__ float tile[32][33];
    const int kb = blockIdx.y * 32, nb = blockIdx.x * 32;
    const int tx = threadIdx.x, ty = threadIdx.y;   // 32 x 8
    #pragma unroll
    for (int i = 0; i < 32; i += 8)
        tile[ty + i][tx] = W[(size_t)(kb + ty + i) * N + nb + tx];
    __syncthreads();
    #pragma unroll
    for (int i = 0; i < 32; i += 8) {
        int n = nb + ty + i, k = kb + tx;
        float v = tile[tx][ty + i];
        bf16 h, l;
        splitb(v, h, l);
        Whi[(size_t)n * K + k] = h;
        Wlo[(size_t)n * K + k] = l;
    }
}

// ---------------- weight transpose to single fp16: W[K][N] -> Wh[N][K] ---------
__global__ void splitwh_t(const float* __restrict__ W,
                          __half* __restrict__ Wh, int K, int N) {
    __shared__ float tile[32][33];
    const int kb = blockIdx.y * 32, nb = blockIdx.x * 32;
    const int tx = threadIdx.x, ty = threadIdx.y;   // 32 x 8
    #pragma unroll
    for (int i = 0; i < 32; i += 8)
        tile[ty + i][tx] = W[(size_t)(kb + ty + i) * N + nb + tx];
    __syncthreads();
    #pragma unroll
    for (int i = 0; i < 32; i += 8) {
        int n = nb + ty + i, k = kb + tx;
        Wh[(size_t)n * K + k] = __float2half(tile[tx][ty + i]);
    }
}

// ---------------- RMSNorm (writes pre-split bf16 hi/lo) ----------------
__global__ void rmsnorm_kernel(const float* __restrict__ x,
                               const float* __restrict__ scale) {
    int t = blockIdx.x;
    const float* row = x + (size_t)t * HDIM;
    float ss = 0.f;
    for (int i = threadIdx.x; i < HDIM; i += blockDim.x) {
        float v = row[i];
        ss += v * v;
    }
    __shared__ float sh[9];
    #pragma unroll
    for (int o = 16; o; o >>= 1) ss += __shfl_xor_sync(0xffffffffu, ss, o);
    int lane = threadIdx.x & 31, wid = threadIdx.x >> 5;
    if (lane == 0) sh[wid] = ss;
    __syncthreads();
    if (threadIdx.x == 0) {
        float s = 0.f;
        for (int i = 0; i < (int)(blockDim.x >> 5); i++) s += sh[i];
        sh[8] = rsqrtf(s / (float)HDIM + 1e-5f);
    }
    __syncthreads();
    float inv = sh[8];
    for (int i = threadIdx.x; i < HDIM; i += blockDim.x) {
        float v = row[i] * inv * scale[i];
        bf16 h, l;
        splitb(v, h, l);
        g_nhi[(size_t)t * HDIM + i] = h;
        g_nlo[(size_t)t * HDIM + i] = l;
    }
}

// ---------------- GEMM common pieces -------------------------------------------
#define MMAB(d, a, b0, b1) asm volatile( \
  "mma.sync.aligned.m16n8k16.row.col.f32.bf16.bf16.f32 " \
  "{%0,%1,%2,%3},{%4,%5,%6,%7},{%8,%9},{%0,%1,%2,%3};\n" \
  : "+f"((d)[0]), "+f"((d)[1]), "+f"((d)[2]), "+f"((d)[3]) \
  : "r"((a)[0]), "r"((a)[1]), "r"((a)[2]), "r"((a)[3]), \
    "r"(b0), "r"(b1))

#define MMAF(d, a, b0, b1) asm volatile( \
  "mma.sync.aligned.m16n8k16.row.col.f32.f16.f16.f32 " \
  "{%0,%1,%2,%3},{%4,%5,%6,%7},{%8,%9},{%0,%1,%2,%3};\n" \
  : "+f"((d)[0]), "+f"((d)[1]), "+f"((d)[2]), "+f"((d)[3]) \
  : "r"((a)[0]), "r"((a)[1]), "r"((a)[2]), "r"((a)[3]), \
    "r"(b0), "r"(b1))

#define LDSM4(r, addr) asm volatile( \
  "ldmatrix.sync.aligned.m8n8.x4.shared.b16 {%0,%1,%2,%3}, [%4];" \
  : "=r"((r)[0]), "=r"((r)[1]), "=r"((r)[2]), "=r"((r)[3]) : "r"(addr))

#define SROWB 80u                 // padded row stride in bytes (40 halves)
#define SAB   (128u * SROWB)      // 10240 B per array
#define STAGEB  (4u * SAB)        // bf16 3-term: Ahi,Alo,Bhi,Blo
#define STAGEB3 (3u * SAB)        // fp16 2-term: Ahi,Alo,Bh
#define GSMEM_BYTES  (2 * STAGEB)    // 81920
#define GSMEM_BYTES3 (2 * STAGEB3)   // 61440

extern __shared__ unsigned char dynsm[];

// ---------------- split-bf16 3-term GEMM (QKV) ---------------------------------
__global__ __launch_bounds__(512, 2) void gemm_bf16(
    const bf16* __restrict__ Ahi, const bf16* __restrict__ Alo,
    const bf16* __restrict__ Bhi, const bf16* __restrict__ Blo,
    const float* __restrict__ bias,
    float* __restrict__ C, int N, int K)
{
    const int tid  = threadIdx.x;
    const int lane = tid & 31;
    const int wid  = tid >> 5;
    const int grp  = lane >> 2;
    const int qid  = lane & 3;
    const int wm   = (wid >> 2) * 32;
    const int wn   = (wid & 3) * 32;
    const int m0 = blockIdx.y * 128;
    const int n0 = blockIdx.x * 128;

    uint32_t smb;
    asm("{ .reg .u64 t; cvta.to.shared.u64 t, %1; cvt.u32.u64 %0, t; }"
        : "=r"(smb) : "l"(dynsm));

    float acc[2][4][4];
    #pragma unroll
    for (int i = 0; i < 2; i++)
        #pragma unroll
        for (int j = 0; j < 4; j++)
            #pragma unroll
            for (int r = 0; r < 4; r++) acc[i][j][r] = 0.f;

    const int lrow = tid >> 2, lc16 = tid & 3;

    auto load_stage = [&](int stage, int t) {
        const int k0 = t << 5;
        const uint32_t sb = smb + stage * STAGEB;
        {
            const bf16* src = Ahi + (size_t)(m0 + lrow) * K + k0 + lc16 * 8;
            uint32_t dst = sb + lrow * SROWB + lc16 * 16;
            asm volatile("cp.async.cg.shared.global [%0], [%1], 16;" :: "r"(dst), "l"(src));
        }
        {
            const bf16* src = Alo + (size_t)(m0 + lrow) * K + k0 + lc16 * 8;
            uint32_t dst = sb + SAB + lrow * SROWB + lc16 * 16;
            asm volatile("cp.async.cg.shared.global [%0], [%1], 16;" :: "r"(dst), "l"(src));
        }
        {
            const bf16* src = Bhi + (size_t)(n0 + lrow) * K + k0 + lc16 * 8;
            uint32_t dst = sb + 2 * SAB + lrow * SROWB + lc16 * 16;
            asm volatile("cp.async.cg.shared.global [%0], [%1], 16;" :: "r"(dst), "l"(src));
        }
        {
            const bf16* src = Blo + (size_t)(n0 + lrow) * K + k0 + lc16 * 8;
            uint32_t dst = sb + 3 * SAB + lrow * SROWB + lc16 * 16;
            asm volatile("cp.async.cg.shared.global [%0], [%1], 16;" :: "r"(dst), "l"(src));
        }
        asm volatile("cp.async.commit_group;");
    };

    const uint32_t lmrow = lane & 15;
    const uint32_t lmkh  = (lane >> 4) * 16;
    const uint32_t aoff0 = (wm + 0  + lmrow) * SROWB + lmkh;
    const uint32_t aoff1 = (wm + 16 + lmrow) * SROWB + lmkh;
    const uint32_t boff0 = (wn + 0  + lmrow) * SROWB + lmkh;
    const uint32_t boff1 = (wn + 16 + lmrow) * SROWB + lmkh;

    const int trips = K >> 5;
    load_stage(0, 0);
    load_stage(1, 1);

    for (int t = 0; t < trips; t++) {
        if (t < trips - 1) asm volatile("cp.async.wait_group 1;");
        else               asm volatile("cp.async.wait_group 0;");
        __syncthreads();

        const uint32_t sb = smb + (t & 1) * STAGEB;
        #pragma unroll
        for (int ks = 0; ks < 2; ks++) {
            const uint32_t ko = ks * 32;
            uint32_t ah[2][4], al[2][4];
            LDSM4(ah[0], sb + aoff0 + ko);
            LDSM4(ah[1], sb + aoff1 + ko);
            LDSM4(al[0], sb + SAB + aoff0 + ko);
            LDSM4(al[1], sb + SAB + aoff1 + ko);
            #pragma unroll
            for (int np = 0; np < 2; np++) {
                uint32_t bh[4], bl[4];
                LDSM4(bh, sb + 2 * SAB + (np ? boff1 : boff0) + ko);
                LDSM4(bl, sb + 3 * SAB + (np ? boff1 : boff0) + ko);
                #pragma unroll
                for (int mt = 0; mt < 2; mt++) {
                    #pragma unroll
                    for (int sub = 0; sub < 2; sub++) {
                        float* d = acc[mt][np * 2 + sub];
                        MMAB(d, ah[mt], bh[sub], bh[sub + 2]);
                        MMAB(d, ah[mt], bl[sub], bl[sub + 2]);
                        MMAB(d, al[mt], bh[sub], bh[sub + 2]);
                    }
                }
            }
        }
        __syncthreads();
        if (t + 2 < trips) load_stage(t & 1, t + 2);
    }

    #pragma unroll
    for (int mt = 0; mt < 2; mt++) {
        int r0 = m0 + wm + mt * 16 + grp;
        #pragma unroll
        for (int nt = 0; nt < 4; nt++) {
            int c = n0 + wn + nt * 8 + qid * 2;
            float2 bb = *(const float2*)&bias[c];
            float2 v0 = make_float2(acc[mt][nt][0] + bb.x, acc[mt][nt][1] + bb.y);
            float2 v1 = make_float2(acc[mt][nt][2] + bb.x, acc[mt][nt][3] + bb.y);
            *(float2*)&C[(size_t)r0 * N + c]       = v0;
            *(float2*)&C[(size_t)(r0 + 8) * N + c] = v1;
        }
    }
}

// ---------------- fp16 2-term GEMM (out-proj): (Ahi+Alo) @ Bh + bias + resid ----
__global__ __launch_bounds__(512, 2) void gemm_f16(
    const __half* __restrict__ Ahi, const __half* __restrict__ Alo,
    const __half* __restrict__ Bh,
    const float* __restrict__ bias, const float* __restrict__ resid,
    float* __restrict__ C, int N, int K)
{
    const int tid  = threadIdx.x;
    const int lane = tid & 31;
    const int wid  = tid >> 5;
    const int grp  = lane >> 2;
    const int qid  = lane & 3;
    const int wm   = (wid >> 2) * 32;
    const int wn   = (wid & 3) * 32;
    const int m0 = blockIdx.y * 128;
    const int n0 = blockIdx.x * 128;

    uint32_t smb;
    asm("{ .reg .u64 t; cvta.to.shared.u64 t, %1; cvt.u32.u64 %0, t; }"
        : "=r"(smb) : "l"(dynsm));

    float acc[2][4][4];
    #pragma unroll
    for (int i = 0; i < 2; i++)
        #pragma unroll
        for (int j = 0; j < 4; j++)
            #pragma unroll
            for (int r = 0; r < 4; r++) acc[i][j][r] = 0.f;

    const int lrow = tid >> 2, lc16 = tid & 3;

    auto load_stage = [&](int stage, int t) {
        const int k0 = t << 5;
        const uint32_t sb = smb + stage * STAGEB3;
        {
            const __half* src = Ahi + (size_t)(m0 + lrow) * K + k0 + lc16 * 8;
            uint32_t dst = sb + lrow * SROWB + lc16 * 16;
            asm volatile("cp.async.cg.shared.global [%0], [%1], 16;" :: "r"(dst), "l"(src));
        }
        {
            const __half* src = Alo + (size_t)(m0 + lrow) * K + k0 + lc16 * 8;
            uint32_t dst = sb + SAB + lrow * SROWB + lc16 * 16;
            asm volatile("cp.async.cg.shared.global [%0], [%1], 16;" :: "r"(dst), "l"(src));
        }
        {
            const __half* src = Bh + (size_t)(n0 + lrow) * K + k0 + lc16 * 8;
            uint32_t dst = sb + 2 * SAB + lrow * SROWB + lc16 * 16;
            asm volatile("cp.async.cg.shared.global [%0], [%1], 16;" :: "r"(dst), "l"(src));
        }
        asm volatile("cp.async.commit_group;");
    };

    const uint32_t lmrow = lane & 15;
    const uint32_t lmkh  = (lane >> 4) * 16;
    const uint32_t aoff0 = (wm + 0  + lmrow) * SROWB + lmkh;
    const uint32_t aoff1 = (wm + 16 + lmrow) * SROWB + lmkh;
    const uint32_t boff0 = (wn + 0  + lmrow) * SROWB + lmkh;
    const uint32_t boff1 = (wn + 16 + lmrow) * SROWB + lmkh;

    const int trips = K >> 5;
    load_stage(0, 0);
    load_stage(1, 1);

    for (int t = 0; t < trips; t++) {
        if (t < trips - 1) asm volatile("cp.async.wait_group 1;");
        else               asm volatile("cp.async.wait_group 0;");
        __syncthreads();

        const uint32_t sb = smb + (t & 1) * STAGEB3;
        #pragma unroll
        for (int ks = 0; ks < 2; ks++) {
            const uint32_t ko = ks * 32;
            uint32_t ah[2][4], al[2][4];
            LDSM4(ah[0], sb + aoff0 + ko);
            LDSM4(ah[1], sb + aoff1 + ko);
            LDSM4(al[0], sb + SAB + aoff0 + ko);
            LDSM4(al[1], sb + SAB + aoff1 + ko);
            #pragma unroll
            for (int np = 0; np < 2; np++) {
                uint32_t bh[4];
                LDSM4(bh, sb + 2 * SAB + (np ? boff1 : boff0) + ko);
                #pragma unroll
                for (int mt = 0; mt < 2; mt++) {
                    #pragma unroll
                    for (int sub = 0; sub < 2; sub++) {
                        float* d = acc[mt][np * 2 + sub];
                        MMAF(d, ah[mt], bh[sub], bh[sub + 2]);
                        MMAF(d, al[mt], bh[sub], bh[sub + 2]);
                    }
                }
            }
        }
        __syncthreads();
        if (t + 2 < trips) load_stage(t & 1, t + 2);
    }

    #pragma unroll
    for (int mt = 0; mt < 2; mt++) {
        int r0 = m0 + wm + mt * 16 + grp;
        #pragma unroll
        for (int nt = 0; nt < 4; nt++) {
            int c = n0 + wn + nt * 8 + qid * 2;
            float2 bb = *(const float2*)&bias[c];
            float2 ra = *(const float2*)&resid[(size_t)r0 * N + c];
            float2 rb = *(const float2*)&resid[(size_t)(r0 + 8) * N + c];
            float2 v0 = make_float2(acc[mt][nt][0] + bb.x + ra.x,
                                    acc[mt][nt][1] + bb.y + ra.y);
            float2 v1 = make_float2(acc[mt][nt][2] + bb.x + rb.x,
                                    acc[mt][nt][3] + bb.y + rb.y);
            *(float2*)&C[(size_t)r0 * N + c]       = v0;
            *(float2*)&C[(size_t)(r0 + 8) * N + c] = v1;
        }
    }
}

// ---------------- RoPE (in-place on g_qkv) ----------------
__global__ void rope_kernel(const float* __restrict__ cos_t,
                            const float* __restrict__ sin_t) {
    int t = blockIdx.x;
    const float* c = cos_t + t * 32;
    const float* s = sin_t + t * 32;
    float* rowbase = g_qkv + (size_t)t * QKVD;
    for (int i = threadIdx.x; i < 40 * 32; i += blockDim.x) {
        int head = i >> 5, r = i & 31;
        float* base = rowbase + head * HEADD;
        float x1 = base[r], x2 = base[r + 32];
        float cv = c[r], sv = s[r];
        base[r]      = x1 * cv - x2 * sv;
        base[r + 32] = x2 * cv + x1 * sv;
    }
}

// ---------------- tiled sliding-window GQA attention with sink ----------------
// grid (64 q-tiles, 8 kv heads), 512 threads; 4 GQA heads concurrent;
// each warp handles 8 q in two groups of 4 (LDS amortized across the group).
#define KMAX 160
#define KT_STRIDE 164
#define V_STRIDE 68
#define OFF_KT 0
#define OFF_V  (64 * KT_STRIDE)                    // 10496
#define OFF_Q  (OFF_V + KMAX * V_STRIDE)           // 21376
#define OFF_S  (OFF_Q + 4 * 32 * 64)               // 29568
#define ATT_SMEM_FLOATS (OFF_S + 16 * 4 * KT_STRIDE)  // 40064 -> 160256 B

__global__ __launch_bounds__(512, 1) void attn4_kernel(const float* __restrict__ sinks) {
    float* smf = (float*)dynsm;
    float* KsT = smf + OFF_KT;
    float* Vs  = smf + OFF_V;
    float* Qs  = smf + OFF_Q;
    float* S   = smf + OFF_S;

    const int qt = blockIdx.x;
    const int n  = blockIdx.y;
    const int q0 = qt * 32;
    const int k0 = (q0 - SWIN > 0) ? (q0 - SWIN) : 0;
    const int kcnt = q0 + 32 - k0;
    const int tid = threadIdx.x;
    const int lane = tid & 31, wid = tid >> 5;

    const float* kbase = g_qkv + (size_t)k0 * QKVD + NHEADS * HEADD + n * HEADD;
    const float* vbase = kbase + NKVH * HEADD;

    for (int f = tid; f < kcnt * 16; f += 512) {
        int r = f >> 4, dq = (f & 15) * 4;
        float4 kv = *(const float4*)(kbase + (size_t)r * QKVD + dq);
        KsT[(dq + 0) * KT_STRIDE + r] = kv.x;
        KsT[(dq + 1) * KT_STRIDE + r] = kv.y;
        KsT[(dq + 2) * KT_STRIDE + r] = kv.z;
        KsT[(dq + 3) * KT_STRIDE + r] = kv.w;
        float4 vv = *(const float4*)(vbase + (size_t)r * QKVD + dq);
        *(float4*)&Vs[r * V_STRIDE + dq] = vv;
    }
    for (int f = tid; f < 4 * 32 * 16; f += 512) {
        int g = f >> 9, r = (f >> 4) & 31, dq = (f & 15) * 4;
        *(float4*)&Qs[(g * 32 + r) * 64 + dq] =
            *(const float4*)(g_qkv + (size_t)(q0 + r) * QKVD + (n * 4 + g) * HEADD + dq);
    }
    __syncthreads();

    const int g  = wid & 3;
    const int ww = wid >> 2;
    const int h  = n * 4 + g;
    const float snk = sinks[h];
    float* S4 = S + wid * 4 * KT_STRIDE;     // 4 score rows per warp

    #pragma unroll
    for (int qq = 0; qq < 2; qq++) {
        const int qi0 = ww * 8 + qq * 4;     // first of 4 queries
        float lmax[4] = {-INFINITY, -INFINITY, -INFINITY, -INFINITY};

        // ---- score pass: 4 queries share each K-tile load ----
        for (int kb = lane; kb < 40; kb += 32) {
            const int kk = kb * 4;
            float sc[4][4];
            #pragma unroll
            for (int p = 0; p < 4; p++)
                sc[p][0] = sc[p][1] = sc[p][2] = sc[p][3] = 0.f;
            #pragma unroll
            for (int d = 0; d < 64; d += 4) {
                float4 kv0 = *(const float4*)&KsT[(d + 0) * KT_STRIDE + kk];
                float4 kv1 = *(const float4*)&KsT[(d + 1) * KT_STRIDE + kk];
                float4 kv2 = *(const float4*)&KsT[(d + 2) * KT_STRIDE + kk];
                float4 kv3 = *(const float4*)&KsT[(d + 3) * KT_STRIDE + kk];
                #pragma unroll
                for (int p = 0; p < 4; p++) {
                    float4 q4 = *(const float4*)&Qs[(g * 32 + qi0 + p) * 64 + d];
                    sc[p][0] += q4.x * kv0.x + q4.y * kv1.x + q4.z * kv2.x + q4.w * kv3.x;
                    sc[p][1] += q4.x * kv0.y + q4.y * kv1.y + q4.z * kv2.y + q4.w * kv3.y;
                    sc[p][2] += q4.x * kv0.z + q4.y * kv1.z + q4.z * kv2.z + q4.w * kv3.z;
                    sc[p][3] += q4.x * kv0.w + q4.y * kv1.w + q4.z * kv2.w + q4.w * kv3.w;
                }
            }
            #pragma unroll
            for (int p = 0; p < 4; p++) {
                const int qg = q0 + qi0 + p;
                const int khi = qg - k0;
                int klo = qg - SWIN - k0; if (klo < 0) klo = 0;
                float v0 = (kk + 0 >= klo && kk + 0 <= khi) ? sc[p][0] * 0.125f : -INFINITY;
                float v1 = (kk + 1 >= klo && kk + 1 <= khi) ? sc[p][1] * 0.125f : -INFINITY;
                float v2 = (kk + 2 >= klo && kk + 2 <= khi) ? sc[p][2] * 0.125f : -INFINITY;
                float v3 = (kk + 3 >= klo && kk + 3 <= khi) ? sc[p][3] * 0.125f : -INFINITY;
                *(float4*)&S4[p * KT_STRIDE + kk] = make_float4(v0, v1, v2, v3);
                lmax[p] = fmaxf(lmax[p], fmaxf(fmaxf(v0, v1), fmaxf(v2, v3)));
            }
        }
        float inv[4];
        #pragma unroll
        for (int p = 0; p < 4; p++) {
            float m = lmax[p];
            #pragma unroll
            for (int o = 16; o; o >>= 1)
                m = fmaxf(m, __shfl_xor_sync(0xffffffffu, m, o));
            m = fmaxf(m, snk);
            float lsum = 0.f;
            for (int k = lane; k < KMAX; k += 32) {
                float e = expf(S4[p * KT_STRIDE + k] - m);
                S4[p * KT_STRIDE + k] = e;
                lsum += e;
            }
            #pragma unroll
            for (int o = 16; o; o >>= 1)
                lsum += __shfl_xor_sync(0xffffffffu, lsum, o);
            inv[p] = 1.f / (lsum + expf(snk - m));
        }
        __syncwarp();

        // ---- V pass: 4 queries share each V load ----
        float a[4][2];
        #pragma unroll
        for (int p = 0; p < 4; p++) a[p][0] = a[p][1] = 0.f;
        const int d0 = lane, d1 = lane + 32;
        for (int k = 0; k < kcnt; k++) {
            float v0 = Vs[k * V_STRIDE + d0];
            float v1 = Vs[k * V_STRIDE + d1];
            #pragma unroll
            for (int p = 0; p < 4; p++) {
                float pp = S4[p * KT_STRIDE + k];
                a[p][0] += pp * v0;
                a[p][1] += pp * v1;
            }
        }
        #pragma unroll
        for (int p = 0; p < 4; p++) {
            const int qg = q0 + qi0 + p;
            float r0 = a[p][0] * inv[p], r1 = a[p][1] * inv[p];
            __half h0, l0, h1, l1;
            splith(r0, h0, l0);
            splith(r1, h1, l1);
            size_t o0 = (size_t)qg * HDIM + h * HEADD;
            g_ahi[o0 + d0] = h0; g_alo[o0 + d0] = l0;
            g_ahi[o0 + d1] = h1; g_alo[o0 + d1] = l1;
        }
        __syncwarp();
    }
}

// ---------------- launch ----------------
extern "C" void kernel_launch(void* const* d_in, const int* in_sizes, int n_in,
                              void* d_out, int out_size) {
    const float* x          = (const float*)d_in[0];
    const float* scale      = (const float*)d_in[1];
    const float* sinks      = (const float*)d_in[2];
    const float* qkv_kernel = (const float*)d_in[3];
    const float* qkv_bias   = (const float*)d_in[4];
    const float* out_kernel = (const float*)d_in[5];
    const float* out_bias   = (const float*)d_in[6];
    const float* cos_t      = (const float*)d_in[7];
    const float* sin_t      = (const float*)d_in[8];
    // d_in[9] = mask: unused (sliding window applied structurally)
    float* out = (float*)d_out;

    void *p_qkv, *p_nhi, *p_nlo, *p_ahi, *p_alo, *p_wqhi, *p_wqlo, *p_woh;
    cudaGetSymbolAddress(&p_qkv, g_qkv);
    cudaGetSymbolAddress(&p_nhi, g_nhi);
    cudaGetSymbolAddress(&p_nlo, g_nlo);
    cudaGetSymbolAddress(&p_ahi, g_ahi);
    cudaGetSymbolAddress(&p_alo, g_alo);
    cudaGetSymbolAddress(&p_wqhi, g_wqhi);
    cudaGetSymbolAddress(&p_wqlo, g_wqlo);
    cudaGetSymbolAddress(&p_woh, g_woh);

    static bool attr_set = false;
    if (!attr_set) {
        cudaFuncSetAttribute(gemm_bf16,
                             cudaFuncAttributeMaxDynamicSharedMemorySize, GSMEM_BYTES);
        cudaFuncSetAttribute(gemm_f16,
                             cudaFuncAttributeMaxDynamicSharedMemorySize, GSMEM_BYTES3);
        cudaFuncSetAttribute(attn4_kernel,
                             cudaFuncAttributeMaxDynamicSharedMemorySize,
                             ATT_SMEM_FLOATS * 4);
        attr_set = true;
    }

    // pre-split + transpose weights
    splitw_t<<<dim3(QKVD / 32, HDIM / 32), dim3(32, 8)>>>(
        qkv_kernel, (bf16*)p_wqhi, (bf16*)p_wqlo, HDIM, QKVD);
    splitwh_t<<<dim3(HDIM / 32, HDIM / 32), dim3(32, 8)>>>(
        out_kernel, (__half*)p_woh, HDIM, HDIM);

    rmsnorm_kernel<<<TT, 256>>>(x, scale);

    // QKV: [2048,2048] @ [2048,3072], bf16 3-term
    gemm_bf16<<<dim3(QKVD / 128, TT / 128), 512, GSMEM_BYTES>>>(
        (const bf16*)p_nhi, (const bf16*)p_nlo,
        (const bf16*)p_wqhi, (const bf16*)p_wqlo,
        qkv_bias, (float*)p_qkv, QKVD, HDIM);

    rope_kernel<<<TT, 256>>>(cos_t, sin_t);

    attn4_kernel<<<dim3(TT / 32, NKVH), 512, ATT_SMEM_FLOATS * 4>>>(sinks);

    // out-proj + residual: fp16 2-term
    gemm_f16<<<dim3(HDIM / 128, TT / 128), 512, GSMEM_BYTES3>>>(
        (const __half*)p_ahi, (const __half*)p_alo, (const __half*)p_woh,
        out_bias, x, out, HDIM, HDIM);
}

// round 10
// speedup vs baseline: 1.5289x; 1.1635x over previous
#include <cuda_runtime.h>
#include <cuda_bf16.h>
#include <cuda_fp16.h>
#include <stdint.h>
#include <math.h>

#define TT 2048
#define HDIM 2048
#define NHEADS 32
#define NKVH 8
#define HEADD 64
#define SWIN 128
#define QKVD 3072   // HEADD * (NHEADS + 2*NKVH)

// ---------------- scratch (device globals; no allocation allowed) ----------------
__device__ float g_qkv[(size_t)TT * QKVD];
__device__ __half g_nhi[TT * HDIM];            // rmsnorm out, fp16 hi
__device__ __half g_nlo[TT * HDIM];            // rmsnorm out, fp16 lo
__device__ __half g_ahi[TT * HDIM];            // attention out, fp16 hi
__device__ __half g_alo[TT * HDIM];            // attention out, fp16 lo
__device__ __half g_wqh[(size_t)HDIM * QKVD];  // qkv weight fp16, transposed [N][K]
__device__ __half g_woh[(size_t)HDIM * HDIM];  // out weight fp16, transposed [N][K]

__device__ __forceinline__ void splith(float v, __half& hi, __half& lo) {
    hi = __float2half(v);
    lo = __float2half(v - __half2float(hi));
}

// ---------------- weight transpose to fp16: W[K][N] -> Wh[N][K] ---------
__global__ void splitwh_t(const float* __restrict__ W,
                          __half* __restrict__ Wh, int K, int N) {
    __shared__ float tile[32][33];
    const int kb = blockIdx.y * 32, nb = blockIdx.x * 32;
    const int tx = threadIdx.x, ty = threadIdx.y;   // 32 x 8
    #pragma unroll
    for (int i = 0; i < 32; i += 8)
        tile[ty + i][tx] = W[(size_t)(kb + ty + i) * N + nb + tx];
    __syncthreads();
    #pragma unroll
    for (int i = 0; i < 32; i += 8) {
        int n = nb + ty + i, k = kb + tx;
        Wh[(size_t)n * K + k] = __float2half(tile[tx][ty + i]);
    }
}

// ---------------- RMSNorm (writes pre-split fp16 hi/lo) ----------------
__global__ void rmsnorm_kernel(const float* __restrict__ x,
                               const float* __restrict__ scale) {
    int t = blockIdx.x;
    const float* row = x + (size_t)t * HDIM;
    float ss = 0.f;
    for (int i = threadIdx.x; i < HDIM; i += blockDim.x) {
        float v = row[i];
        ss += v * v;
    }
    __shared__ float sh[9];
    #pragma unroll
    for (int o = 16; o; o >>= 1) ss += __shfl_xor_sync(0xffffffffu, ss, o);
    int lane = threadIdx.x & 31, wid = threadIdx.x >> 5;
    if (lane == 0) sh[wid] = ss;
    __syncthreads();
    if (threadIdx.x == 0) {
        float s = 0.f;
        for (int i = 0; i < (int)(blockDim.x >> 5); i++) s += sh[i];
        sh[8] = rsqrtf(s / (float)HDIM + 1e-5f);
    }
    __syncthreads();
    float inv = sh[8];
    for (int i = threadIdx.x; i < HDIM; i += blockDim.x) {
        float v = row[i] * inv * scale[i];
        __half h, l;
        splith(v, h, l);
        g_nhi[(size_t)t * HDIM + i] = h;
        g_nlo[(size_t)t * HDIM + i] = l;
    }
}

// ---------------- GEMM pieces -------------------------------------------
#define MMAF(d, a, b0, b1) asm volatile( \
  "mma.sync.aligned.m16n8k16.row.col.f32.f16.f16.f32 " \
  "{%0,%1,%2,%3},{%4,%5,%6,%7},{%8,%9},{%0,%1,%2,%3};\n" \
  : "+f"((d)[0]), "+f"((d)[1]), "+f"((d)[2]), "+f"((d)[3]) \
  : "r"((a)[0]), "r"((a)[1]), "r"((a)[2]), "r"((a)[3]), \
    "r"(b0), "r"(b1))

#define LDSM4(r, addr) asm volatile( \
  "ldmatrix.sync.aligned.m8n8.x4.shared.b16 {%0,%1,%2,%3}, [%4];" \
  : "=r"((r)[0]), "=r"((r)[1]), "=r"((r)[2]), "=r"((r)[3]) : "r"(addr))

#define SROWB 80u                 // padded row stride in bytes (40 halves)
#define SAB   (128u * SROWB)      // 10240 B per array
#define STAGEB3 (3u * SAB)        // fp16 2-term: Ahi,Alo,Bh
#define GSMEM_BYTES3 (2 * STAGEB3)   // 61440

extern __shared__ unsigned char dynsm[];

// ---------------- fp16 2-term GEMM: (Ahi+Alo) @ Bh + bias (+ resid) ------------
__global__ __launch_bounds__(512, 2) void gemm_f16(
    const __half* __restrict__ Ahi, const __half* __restrict__ Alo,
    const __half* __restrict__ Bh,
    const float* __restrict__ bias, const float* __restrict__ resid,
    float* __restrict__ C, int N, int K)
{
    const int tid  = threadIdx.x;
    const int lane = tid & 31;
    const int wid  = tid >> 5;
    const int grp  = lane >> 2;
    const int qid  = lane & 3;
    const int wm   = (wid >> 2) * 32;
    const int wn   = (wid & 3) * 32;
    const int m0 = blockIdx.y * 128;
    const int n0 = blockIdx.x * 128;

    uint32_t smb;
    asm("{ .reg .u64 t; cvta.to.shared.u64 t, %1; cvt.u32.u64 %0, t; }"
        : "=r"(smb) : "l"(dynsm));

    float acc[2][4][4];
    #pragma unroll
    for (int i = 0; i < 2; i++)
        #pragma unroll
        for (int j = 0; j < 4; j++)
            #pragma unroll
            for (int r = 0; r < 4; r++) acc[i][j][r] = 0.f;

    const int lrow = tid >> 2, lc16 = tid & 3;

    auto load_stage = [&](int stage, int t) {
        const int k0 = t << 5;
        const uint32_t sb = smb + stage * STAGEB3;
        {
            const __half* src = Ahi + (size_t)(m0 + lrow) * K + k0 + lc16 * 8;
            uint32_t dst = sb + lrow * SROWB + lc16 * 16;
            asm volatile("cp.async.cg.shared.global [%0], [%1], 16;" :: "r"(dst), "l"(src));
        }
        {
            const __half* src = Alo + (size_t)(m0 + lrow) * K + k0 + lc16 * 8;
            uint32_t dst = sb + SAB + lrow * SROWB + lc16 * 16;
            asm volatile("cp.async.cg.shared.global [%0], [%1], 16;" :: "r"(dst), "l"(src));
        }
        {
            const __half* src = Bh + (size_t)(n0 + lrow) * K + k0 + lc16 * 8;
            uint32_t dst = sb + 2 * SAB + lrow * SROWB + lc16 * 16;
            asm volatile("cp.async.cg.shared.global [%0], [%1], 16;" :: "r"(dst), "l"(src));
        }
        asm volatile("cp.async.commit_group;");
    };

    const uint32_t lmrow = lane & 15;
    const uint32_t lmkh  = (lane >> 4) * 16;
    const uint32_t aoff0 = (wm + 0  + lmrow) * SROWB + lmkh;
    const uint32_t aoff1 = (wm + 16 + lmrow) * SROWB + lmkh;
    const uint32_t boff0 = (wn + 0  + lmrow) * SROWB + lmkh;
    const uint32_t boff1 = (wn + 16 + lmrow) * SROWB + lmkh;

    const int trips = K >> 5;
    load_stage(0, 0);
    load_stage(1, 1);

    for (int t = 0; t < trips; t++) {
        if (t < trips - 1) asm volatile("cp.async.wait_group 1;");
        else               asm volatile("cp.async.wait_group 0;");
        __syncthreads();

        const uint32_t sb = smb + (t & 1) * STAGEB3;
        #pragma unroll
        for (int ks = 0; ks < 2; ks++) {
            const uint32_t ko = ks * 32;
            uint32_t ah[2][4], al[2][4];
            LDSM4(ah[0], sb + aoff0 + ko);
            LDSM4(ah[1], sb + aoff1 + ko);
            LDSM4(al[0], sb + SAB + aoff0 + ko);
            LDSM4(al[1], sb + SAB + aoff1 + ko);
            #pragma unroll
            for (int np = 0; np < 2; np++) {
                uint32_t bh[4];
                LDSM4(bh, sb + 2 * SAB + (np ? boff1 : boff0) + ko);
                #pragma unroll
                for (int mt = 0; mt < 2; mt++) {
                    #pragma unroll
                    for (int sub = 0; sub < 2; sub++) {
                        float* d = acc[mt][np * 2 + sub];
                        MMAF(d, ah[mt], bh[sub], bh[sub + 2]);
                        MMAF(d, al[mt], bh[sub], bh[sub + 2]);
                    }
                }
            }
        }
        __syncthreads();
        if (t + 2 < trips) load_stage(t & 1, t + 2);
    }

    #pragma unroll
    for (int mt = 0; mt < 2; mt++) {
        int r0 = m0 + wm + mt * 16 + grp;
        #pragma unroll
        for (int nt = 0; nt < 4; nt++) {
            int c = n0 + wn + nt * 8 + qid * 2;
            float2 bb = *(const float2*)&bias[c];
            float2 v0 = make_float2(acc[mt][nt][0] + bb.x, acc[mt][nt][1] + bb.y);
            float2 v1 = make_float2(acc[mt][nt][2] + bb.x, acc[mt][nt][3] + bb.y);
            if (resid) {
                float2 ra = *(const float2*)&resid[(size_t)r0 * N + c];
                float2 rb = *(const float2*)&resid[(size_t)(r0 + 8) * N + c];
                v0.x += ra.x; v0.y += ra.y; v1.x += rb.x; v1.y += rb.y;
            }
            *(float2*)&C[(size_t)r0 * N + c]       = v0;
            *(float2*)&C[(size_t)(r0 + 8) * N + c] = v1;
        }
    }
}

// ---------------- RoPE (in-place on g_qkv) ----------------
__global__ void rope_kernel(const float* __restrict__ cos_t,
                            const float* __restrict__ sin_t) {
    int t = blockIdx.x;
    const float* c = cos_t + t * 32;
    const float* s = sin_t + t * 32;
    float* rowbase = g_qkv + (size_t)t * QKVD;
    for (int i = threadIdx.x; i < 40 * 32; i += blockDim.x) {
        int head = i >> 5, r = i & 31;
        float* base = rowbase + head * HEADD;
        float x1 = base[r], x2 = base[r + 32];
        float cv = c[r], sv = s[r];
        base[r]      = x1 * cv - x2 * sv;
        base[r + 32] = x2 * cv + x1 * sv;
    }
}

// ---------------- tiled sliding-window GQA attention with sink ----------------
// grid (64 q-tiles, 8 kv heads), 512 threads; 4 GQA heads concurrent;
// each warp handles 8 q in two groups of 4 (LDS amortized across the group).
#define KMAX 160
#define KT_STRIDE 164
#define V_STRIDE 68
#define OFF_KT 0
#define OFF_V  (64 * KT_STRIDE)                    // 10496
#define OFF_Q  (OFF_V + KMAX * V_STRIDE)           // 21376
#define OFF_S  (OFF_Q + 4 * 32 * 64)               // 29568
#define ATT_SMEM_FLOATS (OFF_S + 16 * 4 * KT_STRIDE)  // 40064 -> 160256 B

__global__ __launch_bounds__(512, 1) void attn4_kernel(const float* __restrict__ sinks) {
    float* smf = (float*)dynsm;
    float* KsT = smf + OFF_KT;
    float* Vs  = smf + OFF_V;
    float* Qs  = smf + OFF_Q;
    float* S   = smf + OFF_S;

    const int qt = blockIdx.x;
    const int n  = blockIdx.y;
    const int q0 = qt * 32;
    const int k0 = (q0 - SWIN > 0) ? (q0 - SWIN) : 0;
    const int kcnt = q0 + 32 - k0;
    const int tid = threadIdx.x;
    const int lane = tid & 31, wid = tid >> 5;

    const float* kbase = g_qkv + (size_t)k0 * QKVD + NHEADS * HEADD + n * HEADD;
    const float* vbase = kbase + NKVH * HEADD;

    for (int f = tid; f < kcnt * 16; f += 512) {
        int r = f >> 4, dq = (f & 15) * 4;
        float4 kv = *(const float4*)(kbase + (size_t)r * QKVD + dq);
        KsT[(dq + 0) * KT_STRIDE + r] = kv.x;
        KsT[(dq + 1) * KT_STRIDE + r] = kv.y;
        KsT[(dq + 2) * KT_STRIDE + r] = kv.z;
        KsT[(dq + 3) * KT_STRIDE + r] = kv.w;
        float4 vv = *(const float4*)(vbase + (size_t)r * QKVD + dq);
        *(float4*)&Vs[r * V_STRIDE + dq] = vv;
    }
    for (int f = tid; f < 4 * 32 * 16; f += 512) {
        int g = f >> 9, r = (f >> 4) & 31, dq = (f & 15) * 4;
        *(float4*)&Qs[(g * 32 + r) * 64 + dq] =
            *(const float4*)(g_qkv + (size_t)(q0 + r) * QKVD + (n * 4 + g) * HEADD + dq);
    }
    __syncthreads();

    const int g  = wid & 3;
    const int ww = wid >> 2;
    const int h  = n * 4 + g;
    const float snk = sinks[h];
    float* S4 = S + wid * 4 * KT_STRIDE;     // 4 score rows per warp

    #pragma unroll
    for (int qq = 0; qq < 2; qq++) {
        const int qi0 = ww * 8 + qq * 4;     // first of 4 queries
        float lmax[4] = {-INFINITY, -INFINITY, -INFINITY, -INFINITY};

        // ---- score pass: 4 queries share each K-tile load ----
        for (int kb = lane; kb < 40; kb += 32) {
            const int kk = kb * 4;
            float sc[4][4];
            #pragma unroll
            for (int p = 0; p < 4; p++)
                sc[p][0] = sc[p][1] = sc[p][2] = sc[p][3] = 0.f;
            #pragma unroll
            for (int d = 0; d < 64; d += 4) {
                float4 kv0 = *(const float4*)&KsT[(d + 0) * KT_STRIDE + kk];
                float4 kv1 = *(const float4*)&KsT[(d + 1) * KT_STRIDE + kk];
                float4 kv2 = *(const float4*)&KsT[(d + 2) * KT_STRIDE + kk];
                float4 kv3 = *(const float4*)&KsT[(d + 3) * KT_STRIDE + kk];
                #pragma unroll
                for (int p = 0; p < 4; p++) {
                    float4 q4 = *(const float4*)&Qs[(g * 32 + qi0 + p) * 64 + d];
                    sc[p][0] += q4.x * kv0.x + q4.y * kv1.x + q4.z * kv2.x + q4.w * kv3.x;
                    sc[p][1] += q4.x * kv0.y + q4.y * kv1.y + q4.z * kv2.y + q4.w * kv3.y;
                    sc[p][2] += q4.x * kv0.z + q4.y * kv1.z + q4.z * kv2.z + q4.w * kv3.z;
                    sc[p][3] += q4.x * kv0.w + q4.y * kv1.w + q4.z * kv2.w + q4.w * kv3.w;
                }
            }
            #pragma unroll
            for (int p = 0; p < 4; p++) {
                const int qg = q0 + qi0 + p;
                const int khi = qg - k0;
                int klo = qg - SWIN - k0; if (klo < 0) klo = 0;
                float v0 = (kk + 0 >= klo && kk + 0 <= khi) ? sc[p][0] * 0.125f : -INFINITY;
                float v1 = (kk + 1 >= klo && kk + 1 <= khi) ? sc[p][1] * 0.125f : -INFINITY;
                float v2 = (kk + 2 >= klo && kk + 2 <= khi) ? sc[p][2] * 0.125f : -INFINITY;
                float v3 = (kk + 3 >= klo && kk + 3 <= khi) ? sc[p][3] * 0.125f : -INFINITY;
                *(float4*)&S4[p * KT_STRIDE + kk] = make_float4(v0, v1, v2, v3);
                lmax[p] = fmaxf(lmax[p], fmaxf(fmaxf(v0, v1), fmaxf(v2, v3)));
            }
        }
        float inv[4];
        #pragma unroll
        for (int p = 0; p < 4; p++) {
            float m = lmax[p];
            #pragma unroll
            for (int o = 16; o; o >>= 1)
                m = fmaxf(m, __shfl_xor_sync(0xffffffffu, m, o));
            m = fmaxf(m, snk);
            float lsum = 0.f;
            for (int k = lane; k < KMAX; k += 32) {
                float e = expf(S4[p * KT_STRIDE + k] - m);
                S4[p * KT_STRIDE + k] = e;
                lsum += e;
            }
            #pragma unroll
            for (int o = 16; o; o >>= 1)
                lsum += __shfl_xor_sync(0xffffffffu, lsum, o);
            inv[p] = 1.f / (lsum + expf(snk - m));
        }
        __syncwarp();

        // ---- V pass: 4 queries share each V load ----
        float a[4][2];
        #pragma unroll
        for (int p = 0; p < 4; p++) a[p][0] = a[p][1] = 0.f;
        const int d0 = lane, d1 = lane + 32;
        for (int k = 0; k < kcnt; k++) {
            float v0 = Vs[k * V_STRIDE + d0];
            float v1 = Vs[k * V_STRIDE + d1];
            #pragma unroll
            for (int p = 0; p < 4; p++) {
                float pp = S4[p * KT_STRIDE + k];
                a[p][0] += pp * v0;
                a[p][1] += pp * v1;
            }
        }
        #pragma unroll
        for (int p = 0; p < 4; p++) {
            const int qg = q0 + qi0 + p;
            float r0 = a[p][0] * inv[p], r1 = a[p][1] * inv[p];
            __half h0, l0, h1, l1;
            splith(r0, h0, l0);
            splith(r1, h1, l1);
            size_t o0 = (size_t)qg * HDIM + h * HEADD;
            g_ahi[o0 + d0] = h0; g_alo[o0 + d0] = l0;
            g_ahi[o0 + d1] = h1; g_alo[o0 + d1] = l1;
        }
        __syncwarp();
    }
}

// ---------------- launch ----------------
extern "C" void kernel_launch(void* const* d_in, const int* in_sizes, int n_in,
                              void* d_out, int out_size) {
    const float* x          = (const float*)d_in[0];
    const float* scale      = (const float*)d_in[1];
    const float* sinks      = (const float*)d_in[2];
    const float* qkv_kernel = (const float*)d_in[3];
    const float* qkv_bias   = (const float*)d_in[4];
    const float* out_kernel = (const float*)d_in[5];
    const float* out_bias   = (const float*)d_in[6];
    const float* cos_t      = (const float*)d_in[7];
    const float* sin_t      = (const float*)d_in[8];
    // d_in[9] = mask: unused (sliding window applied structurally)
    float* out = (float*)d_out;

    void *p_qkv, *p_nhi, *p_nlo, *p_ahi, *p_alo, *p_wqh, *p_woh;
    cudaGetSymbolAddress(&p_qkv, g_qkv);
    cudaGetSymbolAddress(&p_nhi, g_nhi);
    cudaGetSymbolAddress(&p_nlo, g_nlo);
    cudaGetSymbolAddress(&p_ahi, g_ahi);
    cudaGetSymbolAddress(&p_alo, g_alo);
    cudaGetSymbolAddress(&p_wqh, g_wqh);
    cudaGetSymbolAddress(&p_woh, g_woh);

    static bool attr_set = false;
    if (!attr_set) {
        cudaFuncSetAttribute(gemm_f16,
                             cudaFuncAttributeMaxDynamicSharedMemorySize, GSMEM_BYTES3);
        cudaFuncSetAttribute(attn4_kernel,
                             cudaFuncAttributeMaxDynamicSharedMemorySize,
                             ATT_SMEM_FLOATS * 4);
        attr_set = true;
    }

    // transpose weights to fp16 [N][K]
    splitwh_t<<<dim3(QKVD / 32, HDIM / 32), dim3(32, 8)>>>(
        qkv_kernel, (__half*)p_wqh, HDIM, QKVD);
    splitwh_t<<<dim3(HDIM / 32, HDIM / 32), dim3(32, 8)>>>(
        out_kernel, (__half*)p_woh, HDIM, HDIM);

    rmsnorm_kernel<<<TT, 256>>>(x, scale);

    // QKV: fp16 2-term [2048,2048] @ [2048,3072]
    gemm_f16<<<dim3(QKVD / 128, TT / 128), 512, GSMEM_BYTES3>>>(
        (const __half*)p_nhi, (const __half*)p_nlo, (const __half*)p_wqh,
        qkv_bias, nullptr, (float*)p_qkv, QKVD, HDIM);

    rope_kernel<<<TT, 256>>>(cos_t, sin_t);

    attn4_kernel<<<dim3(TT / 32, NKVH), 512, ATT_SMEM_FLOATS * 4>>>(sinks);

    // out-proj + residual: fp16 2-term
    gemm_f16<<<dim3(HDIM / 128, TT / 128), 512, GSMEM_BYTES3>>>(
        (const __half*)p_ahi, (const __half*)p_alo, (const __half*)p_woh,
        out_bias, x, out, HDIM, HDIM);
}

// round 11
// speedup vs baseline: 1.8807x; 1.2301x over previous
#include <cuda_runtime.h>
#include <cuda_bf16.h>
#include <cuda_fp16.h>
#include <stdint.h>
#include <math.h>

#define TT 2048
#define HDIM 2048
#define NHEADS 32
#define NKVH 8
#define HEADD 64
#define SWIN 128
#define QKVD 3072   // HEADD * (NHEADS + 2*NKVH)

// ---------------- scratch (device globals; no allocation allowed) ----------------
__device__ float g_qkv[(size_t)TT * QKVD];
__device__ __half g_nh[TT * HDIM];             // rmsnorm out, fp16
__device__ __half g_ahi[TT * HDIM];            // attention out, fp16 hi
__device__ __half g_alo[TT * HDIM];            // attention out, fp16 lo
__device__ __half g_wqh[(size_t)HDIM * QKVD];  // qkv weight fp16, transposed [N][K]
__device__ __half g_woh[(size_t)HDIM * HDIM];  // out weight fp16, transposed [N][K]

__device__ __forceinline__ void splith(float v, __half& hi, __half& lo) {
    hi = __float2half(v);
    lo = __float2half(v - __half2float(hi));
}

// ---------------- weight transpose to fp16: W[K][N] -> Wh[N][K] ---------
__global__ void splitwh_t(const float* __restrict__ W,
                          __half* __restrict__ Wh, int K, int N) {
    __shared__ float tile[32][33];
    const int kb = blockIdx.y * 32, nb = blockIdx.x * 32;
    const int tx = threadIdx.x, ty = threadIdx.y;   // 32 x 8
    #pragma unroll
    for (int i = 0; i < 32; i += 8)
        tile[ty + i][tx] = W[(size_t)(kb + ty + i) * N + nb + tx];
    __syncthreads();
    #pragma unroll
    for (int i = 0; i < 32; i += 8) {
        int n = nb + ty + i, k = kb + tx;
        Wh[(size_t)n * K + k] = __float2half(tile[tx][ty + i]);
    }
}

// ---------------- RMSNorm (writes fp16) ----------------
__global__ void rmsnorm_kernel(const float* __restrict__ x,
                               const float* __restrict__ scale) {
    int t = blockIdx.x;
    const float* row = x + (size_t)t * HDIM;
    float ss = 0.f;
    for (int i = threadIdx.x; i < HDIM; i += blockDim.x) {
        float v = row[i];
        ss += v * v;
    }
    __shared__ float sh[9];
    #pragma unroll
    for (int o = 16; o; o >>= 1) ss += __shfl_xor_sync(0xffffffffu, ss, o);
    int lane = threadIdx.x & 31, wid = threadIdx.x >> 5;
    if (lane == 0) sh[wid] = ss;
    __syncthreads();
    if (threadIdx.x == 0) {
        float s = 0.f;
        for (int i = 0; i < (int)(blockDim.x >> 5); i++) s += sh[i];
        sh[8] = rsqrtf(s / (float)HDIM + 1e-5f);
    }
    __syncthreads();
    float inv = sh[8];
    for (int i = threadIdx.x; i < HDIM; i += blockDim.x)
        g_nh[(size_t)t * HDIM + i] = __float2half(row[i] * inv * scale[i]);
}

// ---------------- GEMM pieces -------------------------------------------
#define MMAF(d, a, b0, b1) asm volatile( \
  "mma.sync.aligned.m16n8k16.row.col.f32.f16.f16.f32 " \
  "{%0,%1,%2,%3},{%4,%5,%6,%7},{%8,%9},{%0,%1,%2,%3};\n" \
  : "+f"((d)[0]), "+f"((d)[1]), "+f"((d)[2]), "+f"((d)[3]) \
  : "r"((a)[0]), "r"((a)[1]), "r"((a)[2]), "r"((a)[3]), \
    "r"(b0), "r"(b1))

#define LDSM4(r, addr) asm volatile( \
  "ldmatrix.sync.aligned.m8n8.x4.shared.b16 {%0,%1,%2,%3}, [%4];" \
  : "=r"((r)[0]), "=r"((r)[1]), "=r"((r)[2]), "=r"((r)[3]) : "r"(addr))

#define SROWB 80u                 // padded row stride in bytes (40 halves)
#define SAB   (128u * SROWB)      // 10240 B per array
#define STAGEB2 (2u * SAB)        // 1-term: A,B
#define STAGEB3 (3u * SAB)        // 2-term: Ahi,Alo,B
#define GSMEM_BYTES2 (2 * STAGEB2)   // 40960
#define GSMEM_BYTES3 (2 * STAGEB3)   // 61440

extern __shared__ unsigned char dynsm[];

// ---------------- fp16 1-term GEMM (QKV): A @ Bh + bias ------------------------
__global__ __launch_bounds__(512, 2) void gemm_f16_1(
    const __half* __restrict__ A, const __half* __restrict__ Bh,
    const float* __restrict__ bias,
    float* __restrict__ C, int N, int K)
{
    const int tid  = threadIdx.x;
    const int lane = tid & 31;
    const int wid  = tid >> 5;
    const int grp  = lane >> 2;
    const int qid  = lane & 3;
    const int wm   = (wid >> 2) * 32;
    const int wn   = (wid & 3) * 32;
    const int m0 = blockIdx.y * 128;
    const int n0 = blockIdx.x * 128;

    uint32_t smb;
    asm("{ .reg .u64 t; cvta.to.shared.u64 t, %1; cvt.u32.u64 %0, t; }"
        : "=r"(smb) : "l"(dynsm));

    float acc[2][4][4];
    #pragma unroll
    for (int i = 0; i < 2; i++)
        #pragma unroll
        for (int j = 0; j < 4; j++)
            #pragma unroll
            for (int r = 0; r < 4; r++) acc[i][j][r] = 0.f;

    const int lrow = tid >> 2, lc16 = tid & 3;

    auto load_stage = [&](int stage, int t) {
        const int k0 = t << 5;
        const uint32_t sb = smb + stage * STAGEB2;
        {
            const __half* src = A + (size_t)(m0 + lrow) * K + k0 + lc16 * 8;
            uint32_t dst = sb + lrow * SROWB + lc16 * 16;
            asm volatile("cp.async.cg.shared.global [%0], [%1], 16;" :: "r"(dst), "l"(src));
        }
        {
            const __half* src = Bh + (size_t)(n0 + lrow) * K + k0 + lc16 * 8;
            uint32_t dst = sb + SAB + lrow * SROWB + lc16 * 16;
            asm volatile("cp.async.cg.shared.global [%0], [%1], 16;" :: "r"(dst), "l"(src));
        }
        asm volatile("cp.async.commit_group;");
    };

    const uint32_t lmrow = lane & 15;
    const uint32_t lmkh  = (lane >> 4) * 16;
    const uint32_t aoff0 = (wm + 0  + lmrow) * SROWB + lmkh;
    const uint32_t aoff1 = (wm + 16 + lmrow) * SROWB + lmkh;
    const uint32_t boff0 = (wn + 0  + lmrow) * SROWB + lmkh;
    const uint32_t boff1 = (wn + 16 + lmrow) * SROWB + lmkh;

    const int trips = K >> 5;
    load_stage(0, 0);
    load_stage(1, 1);

    for (int t = 0; t < trips; t++) {
        if (t < trips - 1) asm volatile("cp.async.wait_group 1;");
        else               asm volatile("cp.async.wait_group 0;");
        __syncthreads();

        const uint32_t sb = smb + (t & 1) * STAGEB2;
        #pragma unroll
        for (int ks = 0; ks < 2; ks++) {
            const uint32_t ko = ks * 32;
            uint32_t ah[2][4];
            LDSM4(ah[0], sb + aoff0 + ko);
            LDSM4(ah[1], sb + aoff1 + ko);
            #pragma unroll
            for (int np = 0; np < 2; np++) {
                uint32_t bh[4];
                LDSM4(bh, sb + SAB + (np ? boff1 : boff0) + ko);
                #pragma unroll
                for (int mt = 0; mt < 2; mt++) {
                    #pragma unroll
                    for (int sub = 0; sub < 2; sub++) {
                        float* d = acc[mt][np * 2 + sub];
                        MMAF(d, ah[mt], bh[sub], bh[sub + 2]);
                    }
                }
            }
        }
        __syncthreads();
        if (t + 2 < trips) load_stage(t & 1, t + 2);
    }

    #pragma unroll
    for (int mt = 0; mt < 2; mt++) {
        int r0 = m0 + wm + mt * 16 + grp;
        #pragma unroll
        for (int nt = 0; nt < 4; nt++) {
            int c = n0 + wn + nt * 8 + qid * 2;
            float2 bb = *(const float2*)&bias[c];
            float2 v0 = make_float2(acc[mt][nt][0] + bb.x, acc[mt][nt][1] + bb.y);
            float2 v1 = make_float2(acc[mt][nt][2] + bb.x, acc[mt][nt][3] + bb.y);
            *(float2*)&C[(size_t)r0 * N + c]       = v0;
            *(float2*)&C[(size_t)(r0 + 8) * N + c] = v1;
        }
    }
}

// ---------------- fp16 2-term GEMM (out-proj): (Ahi+Alo) @ Bh + bias + resid ---
__global__ __launch_bounds__(512, 2) void gemm_f16(
    const __half* __restrict__ Ahi, const __half* __restrict__ Alo,
    const __half* __restrict__ Bh,
    const float* __restrict__ bias, const float* __restrict__ resid,
    float* __restrict__ C, int N, int K)
{
    const int tid  = threadIdx.x;
    const int lane = tid & 31;
    const int wid  = tid >> 5;
    const int grp  = lane >> 2;
    const int qid  = lane & 3;
    const int wm   = (wid >> 2) * 32;
    const int wn   = (wid & 3) * 32;
    const int m0 = blockIdx.y * 128;
    const int n0 = blockIdx.x * 128;

    uint32_t smb;
    asm("{ .reg .u64 t; cvta.to.shared.u64 t, %1; cvt.u32.u64 %0, t; }"
        : "=r"(smb) : "l"(dynsm));

    float acc[2][4][4];
    #pragma unroll
    for (int i = 0; i < 2; i++)
        #pragma unroll
        for (int j = 0; j < 4; j++)
            #pragma unroll
            for (int r = 0; r < 4; r++) acc[i][j][r] = 0.f;

    const int lrow = tid >> 2, lc16 = tid & 3;

    auto load_stage = [&](int stage, int t) {
        const int k0 = t << 5;
        const uint32_t sb = smb + stage * STAGEB3;
        {
            const __half* src = Ahi + (size_t)(m0 + lrow) * K + k0 + lc16 * 8;
            uint32_t dst = sb + lrow * SROWB + lc16 * 16;
            asm volatile("cp.async.cg.shared.global [%0], [%1], 16;" :: "r"(dst), "l"(src));
        }
        {
            const __half* src = Alo + (size_t)(m0 + lrow) * K + k0 + lc16 * 8;
            uint32_t dst = sb + SAB + lrow * SROWB + lc16 * 16;
            asm volatile("cp.async.cg.shared.global [%0], [%1], 16;" :: "r"(dst), "l"(src));
        }
        {
            const __half* src = Bh + (size_t)(n0 + lrow) * K + k0 + lc16 * 8;
            uint32_t dst = sb + 2 * SAB + lrow * SROWB + lc16 * 16;
            asm volatile("cp.async.cg.shared.global [%0], [%1], 16;" :: "r"(dst), "l"(src));
        }
        asm volatile("cp.async.commit_group;");
    };

    const uint32_t lmrow = lane & 15;
    const uint32_t lmkh  = (lane >> 4) * 16;
    const uint32_t aoff0 = (wm + 0  + lmrow) * SROWB + lmkh;
    const uint32_t aoff1 = (wm + 16 + lmrow) * SROWB + lmkh;
    const uint32_t boff0 = (wn + 0  + lmrow) * SROWB + lmkh;
    const uint32_t boff1 = (wn + 16 + lmrow) * SROWB + lmkh;

    const int trips = K >> 5;
    load_stage(0, 0);
    load_stage(1, 1);

    for (int t = 0; t < trips; t++) {
        if (t < trips - 1) asm volatile("cp.async.wait_group 1;");
        else               asm volatile("cp.async.wait_group 0;");
        __syncthreads();

        const uint32_t sb = smb + (t & 1) * STAGEB3;
        #pragma unroll
        for (int ks = 0; ks < 2; ks++) {
            const uint32_t ko = ks * 32;
            uint32_t ah[2][4], al[2][4];
            LDSM4(ah[0], sb + aoff0 + ko);
            LDSM4(ah[1], sb + aoff1 + ko);
            LDSM4(al[0], sb + SAB + aoff0 + ko);
            LDSM4(al[1], sb + SAB + aoff1 + ko);
            #pragma unroll
            for (int np = 0; np < 2; np++) {
                uint32_t bh[4];
                LDSM4(bh, sb + 2 * SAB + (np ? boff1 : boff0) + ko);
                #pragma unroll
                for (int mt = 0; mt < 2; mt++) {
                    #pragma unroll
                    for (int sub = 0; sub < 2; sub++) {
                        float* d = acc[mt][np * 2 + sub];
                        MMAF(d, ah[mt], bh[sub], bh[sub + 2]);
                        MMAF(d, al[mt], bh[sub], bh[sub + 2]);
                    }
                }
            }
        }
        __syncthreads();
        if (t + 2 < trips) load_stage(t & 1, t + 2);
    }

    #pragma unroll
    for (int mt = 0; mt < 2; mt++) {
        int r0 = m0 + wm + mt * 16 + grp;
        #pragma unroll
        for (int nt = 0; nt < 4; nt++) {
            int c = n0 + wn + nt * 8 + qid * 2;
            float2 bb = *(const float2*)&bias[c];
            float2 ra = *(const float2*)&resid[(size_t)r0 * N + c];
            float2 rb = *(const float2*)&resid[(size_t)(r0 + 8) * N + c];
            float2 v0 = make_float2(acc[mt][nt][0] + bb.x + ra.x,
                                    acc[mt][nt][1] + bb.y + ra.y);
            float2 v1 = make_float2(acc[mt][nt][2] + bb.x + rb.x,
                                    acc[mt][nt][3] + bb.y + rb.y);
            *(float2*)&C[(size_t)r0 * N + c]       = v0;
            *(float2*)&C[(size_t)(r0 + 8) * N + c] = v1;
        }
    }
}

// ---------------- RoPE (in-place on g_qkv) ----------------
__global__ void rope_kernel(const float* __restrict__ cos_t,
                            const float* __restrict__ sin_t) {
    int t = blockIdx.x;
    const float* c = cos_t + t * 32;
    const float* s = sin_t + t * 32;
    float* rowbase = g_qkv + (size_t)t * QKVD;
    for (int i = threadIdx.x; i < 40 * 32; i += blockDim.x) {
        int head = i >> 5, r = i & 31;
        float* base = rowbase + head * HEADD;
        float x1 = base[r], x2 = base[r + 32];
        float cv = c[r], sv = s[r];
        base[r]      = x1 * cv - x2 * sv;
        base[r + 32] = x2 * cv + x1 * sv;
    }
}

// ---------------- tiled sliding-window GQA attention with sink ----------------
#define KMAX 160
#define KT_STRIDE 164
#define V_STRIDE 68
#define OFF_KT 0
#define OFF_V  (64 * KT_STRIDE)                    // 10496
#define OFF_Q  (OFF_V + KMAX * V_STRIDE)           // 21376
#define OFF_S  (OFF_Q + 4 * 32 * 64)               // 29568
#define ATT_SMEM_FLOATS (OFF_S + 16 * 4 * KT_STRIDE)  // 40064 -> 160256 B

__global__ __launch_bounds__(512, 1) void attn4_kernel(const float* __restrict__ sinks) {
    float* smf = (float*)dynsm;
    float* KsT = smf + OFF_KT;
    float* Vs  = smf + OFF_V;
    float* Qs  = smf + OFF_Q;
    float* S   = smf + OFF_S;

    const int qt = blockIdx.x;
    const int n  = blockIdx.y;
    const int q0 = qt * 32;
    const int k0 = (q0 - SWIN > 0) ? (q0 - SWIN) : 0;
    const int kcnt = q0 + 32 - k0;
    const int tid = threadIdx.x;
    const int lane = tid & 31, wid = tid >> 5;

    const float* kbase = g_qkv + (size_t)k0 * QKVD + NHEADS * HEADD + n * HEADD;
    const float* vbase = kbase + NKVH * HEADD;

    for (int f = tid; f < kcnt * 16; f += 512) {
        int r = f >> 4, dq = (f & 15) * 4;
        float4 kv = *(const float4*)(kbase + (size_t)r * QKVD + dq);
        KsT[(dq + 0) * KT_STRIDE + r] = kv.x;
        KsT[(dq + 1) * KT_STRIDE + r] = kv.y;
        KsT[(dq + 2) * KT_STRIDE + r] = kv.z;
        KsT[(dq + 3) * KT_STRIDE + r] = kv.w;
        float4 vv = *(const float4*)(vbase + (size_t)r * QKVD + dq);
        *(float4*)&Vs[r * V_STRIDE + dq] = vv;
    }
    for (int f = tid; f < 4 * 32 * 16; f += 512) {
        int g = f >> 9, r = (f >> 4) & 31, dq = (f & 15) * 4;
        *(float4*)&Qs[(g * 32 + r) * 64 + dq] =
            *(const float4*)(g_qkv + (size_t)(q0 + r) * QKVD + (n * 4 + g) * HEADD + dq);
    }
    __syncthreads();

    const int g  = wid & 3;
    const int ww = wid >> 2;
    const int h  = n * 4 + g;
    const float snk = sinks[h];
    float* S4 = S + wid * 4 * KT_STRIDE;

    #pragma unroll
    for (int qq = 0; qq < 2; qq++) {
        const int qi0 = ww * 8 + qq * 4;
        float lmax[4] = {-INFINITY, -INFINITY, -INFINITY, -INFINITY};

        for (int kb = lane; kb < 40; kb += 32) {
            const int kk = kb * 4;
            float sc[4][4];
            #pragma unroll
            for (int p = 0; p < 4; p++)
                sc[p][0] = sc[p][1] = sc[p][2] = sc[p][3] = 0.f;
            #pragma unroll
            for (int d = 0; d < 64; d += 4) {
                float4 kv0 = *(const float4*)&KsT[(d + 0) * KT_STRIDE + kk];
                float4 kv1 = *(const float4*)&KsT[(d + 1) * KT_STRIDE + kk];
                float4 kv2 = *(const float4*)&KsT[(d + 2) * KT_STRIDE + kk];
                float4 kv3 = *(const float4*)&KsT[(d + 3) * KT_STRIDE + kk];
                #pragma unroll
                for (int p = 0; p < 4; p++) {
                    float4 q4 = *(const float4*)&Qs[(g * 32 + qi0 + p) * 64 + d];
                    sc[p][0] += q4.x * kv0.x + q4.y * kv1.x + q4.z * kv2.x + q4.w * kv3.x;
                    sc[p][1] += q4.x * kv0.y + q4.y * kv1.y + q4.z * kv2.y + q4.w * kv3.y;
                    sc[p][2] += q4.x * kv0.z + q4.y * kv1.z + q4.z * kv2.z + q4.w * kv3.z;
                    sc[p][3] += q4.x * kv0.w + q4.y * kv1.w + q4.z * kv2.w + q4.w * kv3.w;
                }
            }
            #pragma unroll
            for (int p = 0; p < 4; p++) {
                const int qg = q0 + qi0 + p;
                const int khi = qg - k0;
                int klo = qg - SWIN - k0; if (klo < 0) klo = 0;
                float v0 = (kk + 0 >= klo && kk + 0 <= khi) ? sc[p][0] * 0.125f : -INFINITY;
                float v1 = (kk + 1 >= klo && kk + 1 <= khi) ? sc[p][1] * 0.125f : -INFINITY;
                float v2 = (kk + 2 >= klo && kk + 2 <= khi) ? sc[p][2] * 0.125f : -INFINITY;
                float v3 = (kk + 3 >= klo && kk + 3 <= khi) ? sc[p][3] * 0.125f : -INFINITY;
                *(float4*)&S4[p * KT_STRIDE + kk] = make_float4(v0, v1, v2, v3);
                lmax[p] = fmaxf(lmax[p], fmaxf(fmaxf(v0, v1), fmaxf(v2, v3)));
            }
        }
        float inv[4];
        #pragma unroll
        for (int p = 0; p < 4; p++) {
            float m = lmax[p];
            #pragma unroll
            for (int o = 16; o; o >>= 1)
                m = fmaxf(m, __shfl_xor_sync(0xffffffffu, m, o));
            m = fmaxf(m, snk);
            float lsum = 0.f;
            for (int k = lane; k < KMAX; k += 32) {
                float e = expf(S4[p * KT_STRIDE + k] - m);
                S4[p * KT_STRIDE + k] = e;
                lsum += e;
            }
            #pragma unroll
            for (int o = 16; o; o >>= 1)
                lsum += __shfl_xor_sync(0xffffffffu, lsum, o);
            inv[p] = 1.f / (lsum + expf(snk - m));
        }
        __syncwarp();

        float a[4][2];
        #pragma unroll
        for (int p = 0; p < 4; p++) a[p][0] = a[p][1] = 0.f;
        const int d0 = lane, d1 = lane + 32;
        for (int k = 0; k < kcnt; k++) {
            float v0 = Vs[k * V_STRIDE + d0];
            float v1 = Vs[k * V_STRIDE + d1];
            #pragma unroll
            for (int p = 0; p < 4; p++) {
                float pp = S4[p * KT_STRIDE + k];
                a[p][0] += pp * v0;
                a[p][1] += pp * v1;
            }
        }
        #pragma unroll
        for (int p = 0; p < 4; p++) {
            const int qg = q0 + qi0 + p;
            float r0 = a[p][0] * inv[p], r1 = a[p][1] * inv[p];
            __half h0, l0, h1, l1;
            splith(r0, h0, l0);
            splith(r1, h1, l1);
            size_t o0 = (size_t)qg * HDIM + h * HEADD;
            g_ahi[o0 + d0] = h0; g_alo[o0 + d0] = l0;
            g_ahi[o0 + d1] = h1; g_alo[o0 + d1] = l1;
        }
        __syncwarp();
    }
}

// ---------------- launch ----------------
extern "C" void kernel_launch(void* const* d_in, const int* in_sizes, int n_in,
                              void* d_out, int out_size) {
    const float* x          = (const float*)d_in[0];
    const float* scale      = (const float*)d_in[1];
    const float* sinks      = (const float*)d_in[2];
    const float* qkv_kernel = (const float*)d_in[3];
    const float* qkv_bias   = (const float*)d_in[4];
    const float* out_kernel = (const float*)d_in[5];
    const float* out_bias   = (const float*)d_in[6];
    const float* cos_t      = (const float*)d_in[7];
    const float* sin_t      = (const float*)d_in[8];
    // d_in[9] = mask: unused (sliding window applied structurally)
    float* out = (float*)d_out;

    void *p_qkv, *p_nh, *p_ahi, *p_alo, *p_wqh, *p_woh;
    cudaGetSymbolAddress(&p_qkv, g_qkv);
    cudaGetSymbolAddress(&p_nh, g_nh);
    cudaGetSymbolAddress(&p_ahi, g_ahi);
    cudaGetSymbolAddress(&p_alo, g_alo);
    cudaGetSymbolAddress(&p_wqh, g_wqh);
    cudaGetSymbolAddress(&p_woh, g_woh);

    static bool attr_set = false;
    if (!attr_set) {
        cudaFuncSetAttribute(gemm_f16_1,
                             cudaFuncAttributeMaxDynamicSharedMemorySize, GSMEM_BYTES2);
        cudaFuncSetAttribute(gemm_f16,
                             cudaFuncAttributeMaxDynamicSharedMemorySize, GSMEM_BYTES3);
        cudaFuncSetAttribute(attn4_kernel,
                             cudaFuncAttributeMaxDynamicSharedMemorySize,
                             ATT_SMEM_FLOATS * 4);
        attr_set = true;
    }

    // transpose weights to fp16 [N][K]
    splitwh_t<<<dim3(QKVD / 32, HDIM / 32), dim3(32, 8)>>>(
        qkv_kernel, (__half*)p_wqh, HDIM, QKVD);
    splitwh_t<<<dim3(HDIM / 32, HDIM / 32), dim3(32, 8)>>>(
        out_kernel, (__half*)p_woh, HDIM, HDIM);

    rmsnorm_kernel<<<TT, 256>>>(x, scale);

    // QKV: fp16 1-term [2048,2048] @ [2048,3072]
    gemm_f16_1<<<dim3(QKVD / 128, TT / 128), 512, GSMEM_BYTES2>>>(
        (const __half*)p_nh, (const __half*)p_wqh,
        qkv_bias, (float*)p_qkv, QKVD, HDIM);

    rope_kernel<<<TT, 256>>>(cos_t, sin_t);

    attn4_kernel<<<dim3(TT / 32, NKVH), 512, ATT_SMEM_FLOATS * 4>>>(sinks);

    // out-proj + residual: fp16 2-term
    gemm_f16<<<dim3(HDIM / 128, TT / 128), 512, GSMEM_BYTES3>>>(
        (const __half*)p_ahi, (const __half*)p_alo, (const __half*)p_woh,
        out_bias, x, out, HDIM, HDIM);
}

// round 12
// speedup vs baseline: 2.2765x; 1.2104x over previous
#include <cuda_runtime.h>
#include <cuda_bf16.h>
#include <cuda_fp16.h>
#include <stdint.h>
#include <math.h>

#define TT 2048
#define HDIM 2048
#define NHEADS 32
#define NKVH 8
#define HEADD 64
#define SWIN 128
#define QKVD 3072   // HEADD * (NHEADS + 2*NKVH)

// ---------------- scratch (device globals; no allocation allowed) ----------------
__device__ float g_qkv[(size_t)TT * QKVD];
__device__ __half g_nh[TT * HDIM];             // rmsnorm out, fp16
__device__ __half g_ah[TT * HDIM];             // attention out, fp16
__device__ __half g_wqh[(size_t)HDIM * QKVD];  // qkv weight fp16, transposed [N][K]
__device__ __half g_woh[(size_t)HDIM * HDIM];  // out weight fp16, transposed [N][K]

// ---------------- weight transpose to fp16: W[K][N] -> Wh[N][K] ---------
__global__ void splitwh_t(const float* __restrict__ W,
                          __half* __restrict__ Wh, int K, int N) {
    __shared__ float tile[32][33];
    const int kb = blockIdx.y * 32, nb = blockIdx.x * 32;
    const int tx = threadIdx.x, ty = threadIdx.y;   // 32 x 8
    #pragma unroll
    for (int i = 0; i < 32; i += 8)
        tile[ty + i][tx] = W[(size_t)(kb + ty + i) * N + nb + tx];
    __syncthreads();
    #pragma unroll
    for (int i = 0; i < 32; i += 8) {
        int n = nb + ty + i, k = kb + tx;
        Wh[(size_t)n * K + k] = __float2half(tile[tx][ty + i]);
    }
}

// ---------------- RMSNorm (writes fp16) ----------------
__global__ void rmsnorm_kernel(const float* __restrict__ x,
                               const float* __restrict__ scale) {
    int t = blockIdx.x;
    const float* row = x + (size_t)t * HDIM;
    float ss = 0.f;
    for (int i = threadIdx.x; i < HDIM; i += blockDim.x) {
        float v = row[i];
        ss += v * v;
    }
    __shared__ float sh[9];
    #pragma unroll
    for (int o = 16; o; o >>= 1) ss += __shfl_xor_sync(0xffffffffu, ss, o);
    int lane = threadIdx.x & 31, wid = threadIdx.x >> 5;
    if (lane == 0) sh[wid] = ss;
    __syncthreads();
    if (threadIdx.x == 0) {
        float s = 0.f;
        for (int i = 0; i < (int)(blockDim.x >> 5); i++) s += sh[i];
        sh[8] = rsqrtf(s / (float)HDIM + 1e-5f);
    }
    __syncthreads();
    float inv = sh[8];
    for (int i = threadIdx.x; i < HDIM; i += blockDim.x)
        g_nh[(size_t)t * HDIM + i] = __float2half(row[i] * inv * scale[i]);
}

// ---------------- GEMM pieces -------------------------------------------
#define MMAF(d, a, b0, b1) asm volatile( \
  "mma.sync.aligned.m16n8k16.row.col.f32.f16.f16.f32 " \
  "{%0,%1,%2,%3},{%4,%5,%6,%7},{%8,%9},{%0,%1,%2,%3};\n" \
  : "+f"((d)[0]), "+f"((d)[1]), "+f"((d)[2]), "+f"((d)[3]) \
  : "r"((a)[0]), "r"((a)[1]), "r"((a)[2]), "r"((a)[3]), \
    "r"(b0), "r"(b1))

#define LDSM4(r, addr) asm volatile( \
  "ldmatrix.sync.aligned.m8n8.x4.shared.b16 {%0,%1,%2,%3}, [%4];" \
  : "=r"((r)[0]), "=r"((r)[1]), "=r"((r)[2]), "=r"((r)[3]) : "r"(addr))

#define SROWB 80u                 // padded row stride in bytes (40 halves)
#define SAB   (128u * SROWB)      // 10240 B per array
#define STAGEB2 (2u * SAB)        // A,B
#define GSMEM_BYTES2 (2 * STAGEB2)   // 40960

extern __shared__ unsigned char dynsm[];

// ---------------- fp16 1-term GEMM: A @ Bh + bias (+ resid) --------------------
__global__ __launch_bounds__(512, 2) void gemm_f16_1(
    const __half* __restrict__ A, const __half* __restrict__ Bh,
    const float* __restrict__ bias, const float* __restrict__ resid,
    float* __restrict__ C, int N, int K)
{
    const int tid  = threadIdx.x;
    const int lane = tid & 31;
    const int wid  = tid >> 5;
    const int grp  = lane >> 2;
    const int qid  = lane & 3;
    const int wm   = (wid >> 2) * 32;
    const int wn   = (wid & 3) * 32;
    const int m0 = blockIdx.y * 128;
    const int n0 = blockIdx.x * 128;

    uint32_t smb;
    asm("{ .reg .u64 t; cvta.to.shared.u64 t, %1; cvt.u32.u64 %0, t; }"
        : "=r"(smb) : "l"(dynsm));

    float acc[2][4][4];
    #pragma unroll
    for (int i = 0; i < 2; i++)
        #pragma unroll
        for (int j = 0; j < 4; j++)
            #pragma unroll
            for (int r = 0; r < 4; r++) acc[i][j][r] = 0.f;

    const int lrow = tid >> 2, lc16 = tid & 3;

    auto load_stage = [&](int stage, int t) {
        const int k0 = t << 5;
        const uint32_t sb = smb + stage * STAGEB2;
        {
            const __half* src = A + (size_t)(m0 + lrow) * K + k0 + lc16 * 8;
            uint32_t dst = sb + lrow * SROWB + lc16 * 16;
            asm volatile("cp.async.cg.shared.global [%0], [%1], 16;" :: "r"(dst), "l"(src));
        }
        {
            const __half* src = Bh + (size_t)(n0 + lrow) * K + k0 + lc16 * 8;
            uint32_t dst = sb + SAB + lrow * SROWB + lc16 * 16;
            asm volatile("cp.async.cg.shared.global [%0], [%1], 16;" :: "r"(dst), "l"(src));
        }
        asm volatile("cp.async.commit_group;");
    };

    const uint32_t lmrow = lane & 15;
    const uint32_t lmkh  = (lane >> 4) * 16;
    const uint32_t aoff0 = (wm + 0  + lmrow) * SROWB + lmkh;
    const uint32_t aoff1 = (wm + 16 + lmrow) * SROWB + lmkh;
    const uint32_t boff0 = (wn + 0  + lmrow) * SROWB + lmkh;
    const uint32_t boff1 = (wn + 16 + lmrow) * SROWB + lmkh;

    const int trips = K >> 5;
    load_stage(0, 0);
    load_stage(1, 1);

    for (int t = 0; t < trips; t++) {
        if (t < trips - 1) asm volatile("cp.async.wait_group 1;");
        else               asm volatile("cp.async.wait_group 0;");
        __syncthreads();

        const uint32_t sb = smb + (t & 1) * STAGEB2;
        #pragma unroll
        for (int ks = 0; ks < 2; ks++) {
            const uint32_t ko = ks * 32;
            uint32_t ah[2][4];
            LDSM4(ah[0], sb + aoff0 + ko);
            LDSM4(ah[1], sb + aoff1 + ko);
            #pragma unroll
            for (int np = 0; np < 2; np++) {
                uint32_t bh[4];
                LDSM4(bh, sb + SAB + (np ? boff1 : boff0) + ko);
                #pragma unroll
                for (int mt = 0; mt < 2; mt++) {
                    #pragma unroll
                    for (int sub = 0; sub < 2; sub++) {
                        float* d = acc[mt][np * 2 + sub];
                        MMAF(d, ah[mt], bh[sub], bh[sub + 2]);
                    }
                }
            }
        }
        __syncthreads();
        if (t + 2 < trips) load_stage(t & 1, t + 2);
    }

    #pragma unroll
    for (int mt = 0; mt < 2; mt++) {
        int r0 = m0 + wm + mt * 16 + grp;
        #pragma unroll
        for (int nt = 0; nt < 4; nt++) {
            int c = n0 + wn + nt * 8 + qid * 2;
            float2 bb = *(const float2*)&bias[c];
            float2 v0 = make_float2(acc[mt][nt][0] + bb.x, acc[mt][nt][1] + bb.y);
            float2 v1 = make_float2(acc[mt][nt][2] + bb.x, acc[mt][nt][3] + bb.y);
            if (resid) {
                float2 ra = *(const float2*)&resid[(size_t)r0 * N + c];
                float2 rb = *(const float2*)&resid[(size_t)(r0 + 8) * N + c];
                v0.x += ra.x; v0.y += ra.y; v1.x += rb.x; v1.y += rb.y;
            }
            *(float2*)&C[(size_t)r0 * N + c]       = v0;
            *(float2*)&C[(size_t)(r0 + 8) * N + c] = v1;
        }
    }
}

// ---------------- RoPE (in-place on g_qkv) ----------------
__global__ void rope_kernel(const float* __restrict__ cos_t,
                            const float* __restrict__ sin_t) {
    int t = blockIdx.x;
    const float* c = cos_t + t * 32;
    const float* s = sin_t + t * 32;
    float* rowbase = g_qkv + (size_t)t * QKVD;
    for (int i = threadIdx.x; i < 40 * 32; i += blockDim.x) {
        int head = i >> 5, r = i & 31;
        float* base = rowbase + head * HEADD;
        float x1 = base[r], x2 = base[r + 32];
        float cv = c[r], sv = s[r];
        base[r]      = x1 * cv - x2 * sv;
        base[r + 32] = x2 * cv + x1 * sv;
    }
}

// ---------------- tiled sliding-window GQA attention with sink ----------------
#define KMAX 160
#define KT_STRIDE 164
#define V_STRIDE 68
#define OFF_KT 0
#define OFF_V  (64 * KT_STRIDE)                    // 10496
#define OFF_Q  (OFF_V + KMAX * V_STRIDE)           // 21376
#define OFF_S  (OFF_Q + 4 * 32 * 64)               // 29568
#define ATT_SMEM_FLOATS (OFF_S + 16 * 4 * KT_STRIDE)  // 40064 -> 160256 B

__global__ __launch_bounds__(512, 1) void attn4_kernel(const float* __restrict__ sinks) {
    float* smf = (float*)dynsm;
    float* KsT = smf + OFF_KT;
    float* Vs  = smf + OFF_V;
    float* Qs  = smf + OFF_Q;
    float* S   = smf + OFF_S;

    const int qt = blockIdx.x;
    const int n  = blockIdx.y;
    const int q0 = qt * 32;
    const int k0 = (q0 - SWIN > 0) ? (q0 - SWIN) : 0;
    const int kcnt = q0 + 32 - k0;
    const int tid = threadIdx.x;
    const int lane = tid & 31, wid = tid >> 5;

    const float* kbase = g_qkv + (size_t)k0 * QKVD + NHEADS * HEADD + n * HEADD;
    const float* vbase = kbase + NKVH * HEADD;

    for (int f = tid; f < kcnt * 16; f += 512) {
        int r = f >> 4, dq = (f & 15) * 4;
        float4 kv = *(const float4*)(kbase + (size_t)r * QKVD + dq);
        KsT[(dq + 0) * KT_STRIDE + r] = kv.x;
        KsT[(dq + 1) * KT_STRIDE + r] = kv.y;
        KsT[(dq + 2) * KT_STRIDE + r] = kv.z;
        KsT[(dq + 3) * KT_STRIDE + r] = kv.w;
        float4 vv = *(const float4*)(vbase + (size_t)r * QKVD + dq);
        *(float4*)&Vs[r * V_STRIDE + dq] = vv;
    }
    for (int f = tid; f < 4 * 32 * 16; f += 512) {
        int g = f >> 9, r = (f >> 4) & 31, dq = (f & 15) * 4;
        *(float4*)&Qs[(g * 32 + r) * 64 + dq] =
            *(const float4*)(g_qkv + (size_t)(q0 + r) * QKVD + (n * 4 + g) * HEADD + dq);
    }
    __syncthreads();

    const int g  = wid & 3;
    const int ww = wid >> 2;
    const int h  = n * 4 + g;
    const float snk = sinks[h];
    float* S4 = S + wid * 4 * KT_STRIDE;

    #pragma unroll
    for (int qq = 0; qq < 2; qq++) {
        const int qi0 = ww * 8 + qq * 4;
        float lmax[4] = {-INFINITY, -INFINITY, -INFINITY, -INFINITY};

        for (int kb = lane; kb < 40; kb += 32) {
            const int kk = kb * 4;
            float sc[4][4];
            #pragma unroll
            for (int p = 0; p < 4; p++)
                sc[p][0] = sc[p][1] = sc[p][2] = sc[p][3] = 0.f;
            #pragma unroll
            for (int d = 0; d < 64; d += 4) {
                float4 kv0 = *(const float4*)&KsT[(d + 0) * KT_STRIDE + kk];
                float4 kv1 = *(const float4*)&KsT[(d + 1) * KT_STRIDE + kk];
                float4 kv2 = *(const float4*)&KsT[(d + 2) * KT_STRIDE + kk];
                float4 kv3 = *(const float4*)&KsT[(d + 3) * KT_STRIDE + kk];
                #pragma unroll
                for (int p = 0; p < 4; p++) {
                    float4 q4 = *(const float4*)&Qs[(g * 32 + qi0 + p) * 64 + d];
                    sc[p][0] += q4.x * kv0.x + q4.y * kv1.x + q4.z * kv2.x + q4.w * kv3.x;
                    sc[p][1] += q4.x * kv0.y + q4.y * kv1.y + q4.z * kv2.y + q4.w * kv3.y;
                    sc[p][2] += q4.x * kv0.z + q4.y * kv1.z + q4.z * kv2.z + q4.w * kv3.z;
                    sc[p][3] += q4.x * kv0.w + q4.y * kv1.w + q4.z * kv2.w + q4.w * kv3.w;
                }
            }
            #pragma unroll
            for (int p = 0; p < 4; p++) {
                const int qg = q0 + qi0 + p;
                const int khi = qg - k0;
                int klo = qg - SWIN - k0; if (klo < 0) klo = 0;
                float v0 = (kk + 0 >= klo && kk + 0 <= khi) ? sc[p][0] * 0.125f : -INFINITY;
                float v1 = (kk + 1 >= klo && kk + 1 <= khi) ? sc[p][1] * 0.125f : -INFINITY;
                float v2 = (kk + 2 >= klo && kk + 2 <= khi) ? sc[p][2] * 0.125f : -INFINITY;
                float v3 = (kk + 3 >= klo && kk + 3 <= khi) ? sc[p][3] * 0.125f : -INFINITY;
                *(float4*)&S4[p * KT_STRIDE + kk] = make_float4(v0, v1, v2, v3);
                lmax[p] = fmaxf(lmax[p], fmaxf(fmaxf(v0, v1), fmaxf(v2, v3)));
            }
        }
        float inv[4];
        #pragma unroll
        for (int p = 0; p < 4; p++) {
            float m = lmax[p];
            #pragma unroll
            for (int o = 16; o; o >>= 1)
                m = fmaxf(m, __shfl_xor_sync(0xffffffffu, m, o));
            m = fmaxf(m, snk);
            float lsum = 0.f;
            for (int k = lane; k < KMAX; k += 32) {
                float e = expf(S4[p * KT_STRIDE + k] - m);
                S4[p * KT_STRIDE + k] = e;
                lsum += e;
            }
            #pragma unroll
            for (int o = 16; o; o >>= 1)
                lsum += __shfl_xor_sync(0xffffffffu, lsum, o);
            inv[p] = 1.f / (lsum + expf(snk - m));
        }
        __syncwarp();

        float a[4][2];
        #pragma unroll
        for (int p = 0; p < 4; p++) a[p][0] = a[p][1] = 0.f;
        const int d0 = lane, d1 = lane + 32;
        for (int k = 0; k < kcnt; k++) {
            float v0 = Vs[k * V_STRIDE + d0];
            float v1 = Vs[k * V_STRIDE + d1];
            #pragma unroll
            for (int p = 0; p < 4; p++) {
                float pp = S4[p * KT_STRIDE + k];
                a[p][0] += pp * v0;
                a[p][1] += pp * v1;
            }
        }
        #pragma unroll
        for (int p = 0; p < 4; p++) {
            const int qg = q0 + qi0 + p;
            size_t o0 = (size_t)qg * HDIM + h * HEADD;
            g_ah[o0 + d0] = __float2half(a[p][0] * inv[p]);
            g_ah[o0 + d1] = __float2half(a[p][1] * inv[p]);
        }
        __syncwarp();
    }
}

// ---------------- launch ----------------
extern "C" void kernel_launch(void* const* d_in, const int* in_sizes, int n_in,
                              void* d_out, int out_size) {
    const float* x          = (const float*)d_in[0];
    const float* scale      = (const float*)d_in[1];
    const float* sinks      = (const float*)d_in[2];
    const float* qkv_kernel = (const float*)d_in[3];
    const float* qkv_bias   = (const float*)d_in[4];
    const float* out_kernel = (const float*)d_in[5];
    const float* out_bias   = (const float*)d_in[6];
    const float* cos_t      = (const float*)d_in[7];
    const float* sin_t      = (const float*)d_in[8];
    // d_in[9] = mask: unused (sliding window applied structurally)
    float* out = (float*)d_out;

    void *p_qkv, *p_nh, *p_ah, *p_wqh, *p_woh;
    cudaGetSymbolAddress(&p_qkv, g_qkv);
    cudaGetSymbolAddress(&p_nh, g_nh);
    cudaGetSymbolAddress(&p_ah, g_ah);
    cudaGetSymbolAddress(&p_wqh, g_wqh);
    cudaGetSymbolAddress(&p_woh, g_woh);

    static bool attr_set = false;
    if (!attr_set) {
        cudaFuncSetAttribute(gemm_f16_1,
                             cudaFuncAttributeMaxDynamicSharedMemorySize, GSMEM_BYTES2);
        cudaFuncSetAttribute(attn4_kernel,
                             cudaFuncAttributeMaxDynamicSharedMemorySize,
                             ATT_SMEM_FLOATS * 4);
        attr_set = true;
    }

    // transpose weights to fp16 [N][K]
    splitwh_t<<<dim3(QKVD / 32, HDIM / 32), dim3(32, 8)>>>(
        qkv_kernel, (__half*)p_wqh, HDIM, QKVD);
    splitwh_t<<<dim3(HDIM / 32, HDIM / 32), dim3(32, 8)>>>(
        out_kernel, (__half*)p_woh, HDIM, HDIM);

    rmsnorm_kernel<<<TT, 256>>>(x, scale);

    // QKV: fp16 1-term [2048,2048] @ [2048,3072]
    gemm_f16_1<<<dim3(QKVD / 128, TT / 128), 512, GSMEM_BYTES2>>>(
        (const __half*)p_nh, (const __half*)p_wqh,
        qkv_bias, nullptr, (float*)p_qkv, QKVD, HDIM);

    rope_kernel<<<TT, 256>>>(cos_t, sin_t);

    attn4_kernel<<<dim3(TT / 32, NKVH), 512, ATT_SMEM_FLOATS * 4>>>(sinks);

    // out-proj + residual: fp16 1-term
    gemm_f16_1<<<dim3(HDIM / 128, TT / 128), 512, GSMEM_BYTES2>>>(
        (const __half*)p_ah, (const __half*)p_woh,
        out_bias, x, out, HDIM, HDIM);
}